// round 8
// baseline (speedup 1.0000x reference)
#include <cuda_runtime.h>
#include <cstdint>

#define NB   32
#define NH   128
#define RS   40        // h row: [0,4) L-halo | [4,36) owned 32 | 36 t128/R-halo | ..39
#define CBLK 1288      // 32*RS + 8 pad  (h block stride per 32 channels, floats)
#define WBLK 12296     // 32*384 + 8 pad (w block stride per 32 channels, floats)
#define NITER 131
#define NTHREADS 1024

#define HS_FLOATS (128*RS + 3*8)        // 5144
#define WS_FLOATS (128*384 + 3*8)       // 49176

typedef unsigned long long u64t;

// ---------- packed f32x2 helpers ----------
__device__ __forceinline__ u64t pk2(float a, float b){
    u64t r; asm("mov.b64 %0, {%1, %2};" : "=l"(r) : "f"(a), "f"(b)); return r;
}
__device__ __forceinline__ void fma2(u64t& d, u64t a, u64t b){
    asm("fma.rn.f32x2 %0, %1, %2, %0;" : "+l"(d) : "l"(a), "l"(b));
}
__device__ __forceinline__ void unpk2(u64t v, float& a, float& b){
    asm("mov.b64 {%0, %1}, %2;" : "=f"(a), "=f"(b) : "l"(v));
}
__device__ __forceinline__ float lo2(u64t v){ float a,b; unpk2(v,a,b); return a; }
__device__ __forceinline__ float hi2(u64t v){ float a,b; unpk2(v,a,b); return b; }

__device__ __forceinline__ uint32_t mapa32(uint32_t addr, uint32_t rank){
    uint32_t r; asm("mapa.shared::cluster.u32 %0, %1, %2;" : "=r"(r) : "r"(addr), "r"(rank));
    return r;
}
__device__ __forceinline__ void st_cl_u64(uint32_t addr, u64t v){
    asm volatile("st.shared::cluster.b64 [%0], %1;" :: "r"(addr), "l"(v) : "memory");
}

#define CLUSTER_SYNC() do { \
    asm volatile("barrier.cluster.arrive.aligned;" ::: "memory"); \
    asm volatile("barrier.cluster.wait.aligned;"   ::: "memory"); } while(0)

// One residual dilated-conv iteration; h resident in smem.
// Lanes: og_lo=lane[0:3), ch2=lane[3:5) (4 channel quarters). Warps: oghi=w[0:3), tt=w[3:5).
// Thread: 2 out-ch x 8 t x 32 ch; two shfl.bfly levels (8,16) complete the 128-ch sum in-warp.
template<int D>
__device__ __forceinline__ void conv_iter(
    float* __restrict__ hs, const float* __restrict__ ws, const float* __restrict__ cb,
    uint32_t lP, uint32_t rP, int tg)
{
    const int tid  = threadIdx.x;
    const int lane = tid & 31;
    const int w    = tid >> 5;
    const int og   = ((w & 7) << 3) | (lane & 7);     // 0..63
    const int ch2  = (lane >> 3) & 3;                 // channel quarter
    const int tt   = (w >> 3) & 3;                    // 0..3, t0 = tt*8
    const bool sp  = (tg == 3) && (tt == 3);          // also produce t=128

    u64t acc[2][4] = {{0ull,0ull,0ull,0ull},{0ull,0ull,0ull,0ull}};
    float accx[2] = {0.f, 0.f};

    // window: 16 floats = local cols [tt*8, tt*8+16); owned outputs at window cols [4,12)
    const char*  hb = (const char*)(hs + ch2*CBLK + tt*8);
    const float* wb = ws + ch2*WBLK + og*2;

    #pragma unroll 1
    for (int cc = 0; cc < 32; cc++){
        ulonglong2 a0 = *(const ulonglong2*)(hb);
        ulonglong2 a1 = *(const ulonglong2*)(hb + 16);
        ulonglong2 a2 = *(const ulonglong2*)(hb + 32);
        ulonglong2 a3 = *(const ulonglong2*)(hb + 48);
        float2 w0 = *(const float2*)(wb);
        float2 w1 = *(const float2*)(wb + 128);
        float2 w2 = *(const float2*)(wb + 256);
        u64t u[8] = {a0.x, a0.y, a1.x, a1.y, a2.x, a2.y, a3.x, a3.y};

        if (D != 1){
            constexpr int S0 = (D == 4) ? 0 : 1;
            constexpr int S2 = (D == 4) ? 4 : 3;
            #define DOO(oi, v0, v1, v2) do {                                   \
                u64t d0 = pk2((v0),(v0)), d1 = pk2((v1),(v1)), d2 = pk2((v2),(v2)); \
                fma2(acc[oi][0], d0, u[S0+0]); fma2(acc[oi][1], d0, u[S0+1]);  \
                fma2(acc[oi][2], d0, u[S0+2]); fma2(acc[oi][3], d0, u[S0+3]);  \
                fma2(acc[oi][0], d1, u[2]);    fma2(acc[oi][1], d1, u[3]);     \
                fma2(acc[oi][2], d1, u[4]);    fma2(acc[oi][3], d1, u[5]);     \
                fma2(acc[oi][0], d2, u[S2+0]); fma2(acc[oi][1], d2, u[S2+1]);  \
                fma2(acc[oi][2], d2, u[S2+2]); fma2(acc[oi][3], d2, u[S2+3]);  \
            } while(0)
            DOO(0, w0.x, w1.x, w2.x);
            DOO(1, w0.y, w1.y, w2.y);
            #undef DOO
        } else {
            float s[16];
            #pragma unroll
            for (int j = 0; j < 8; j++) unpk2(u[j], s[2*j], s[2*j+1]);
            u64t om[6];
            #pragma unroll
            for (int j = 1; j < 6; j++) om[j] = pk2(s[2*j+1], s[2*j+2]);
            #define DOO1(oi, v0, v1, v2) do {                                  \
                u64t d0 = pk2((v0),(v0)), d1 = pk2((v1),(v1)), d2 = pk2((v2),(v2)); \
                fma2(acc[oi][0], d0, om[1]); fma2(acc[oi][1], d0, om[2]);      \
                fma2(acc[oi][2], d0, om[3]); fma2(acc[oi][3], d0, om[4]);      \
                fma2(acc[oi][0], d1, u[2]);  fma2(acc[oi][1], d1, u[3]);       \
                fma2(acc[oi][2], d1, u[4]);  fma2(acc[oi][3], d1, u[5]);       \
                fma2(acc[oi][0], d2, om[2]); fma2(acc[oi][1], d2, om[3]);      \
                fma2(acc[oi][2], d2, om[4]); fma2(acc[oi][3], d2, om[5]);      \
            } while(0)
            DOO1(0, w0.x, w1.x, w2.x);
            DOO1(1, w0.y, w1.y, w2.y);
            #undef DOO1
        }

        if (sp){
            // t=128 at window col 12 (local col 36); tap t+D is zero tail
            const float tm = (D == 4) ? lo2(u[4]) : (D == 2 ? lo2(u[5]) : hi2(u[5]));
            const float tz = lo2(u[6]);
            accx[0] = fmaf(w0.x, tm, fmaf(w1.x, tz, accx[0]));
            accx[1] = fmaf(w0.y, tm, fmaf(w1.y, tz, accx[1]));
        }

        hb += RS*4;
        wb += 384;
    }

    // ---- complete 128-channel sums: butterfly over lane bits 3 and 4 ----
    float res[2][8];
    #pragma unroll
    for (int oi = 0; oi < 2; oi++)
        #pragma unroll
        for (int p = 0; p < 4; p++){
            float a, b; unpk2(acc[oi][p], a, b);
            a += __shfl_xor_sync(0xffffffffu, a, 8);
            b += __shfl_xor_sync(0xffffffffu, b, 8);
            a += __shfl_xor_sync(0xffffffffu, a, 16);
            b += __shfl_xor_sync(0xffffffffu, b, 16);
            res[oi][2*p] = a; res[oi][2*p+1] = b;
        }
    if (sp){
        #pragma unroll
        for (int oi = 0; oi < 2; oi++){
            accx[oi] += __shfl_xor_sync(0xffffffffu, accx[oi], 8);
            accx[oi] += __shfl_xor_sync(0xffffffffu, accx[oi], 16);
        }
    }

    CLUSTER_SYNC();   // (A) all reads of h complete cluster-wide

    // ---- epilogue (lanes 0-7): bias + relu + residual; own cols + peer halos ----
    if (ch2 == 0){
        #pragma unroll
        for (int oi = 0; oi < 2; oi++){
            const int   o    = og*2 + oi;
            const int   ro   = o*RS + (o >> 5)*8;
            const float bias = cb[o];
            float* own = hs + ro + 4 + tt*8;
            float hn[8];
            #pragma unroll
            for (int p = 0; p < 8; p++)
                hn[p] = fmaxf(res[oi][p] + bias, 0.f) + own[p];
            *(float4*)own       = make_float4(hn[0], hn[1], hn[2], hn[3]);
            *(float4*)(own + 4) = make_float4(hn[4], hn[5], hn[6], hn[7]);
            if (tt == 0 && tg > 0){          // first 4 owned cols -> left peer R-halo [36,40)
                st_cl_u64(lP + (uint32_t)(ro + 36)*4u, pk2(hn[0], hn[1]));
                st_cl_u64(lP + (uint32_t)(ro + 38)*4u, pk2(hn[2], hn[3]));
            }
            if (tt == 3 && tg < 3){          // last 4 owned cols -> right peer L-halo [0,4)
                st_cl_u64(rP + (uint32_t)(ro + 0)*4u, pk2(hn[4], hn[5]));
                st_cl_u64(rP + (uint32_t)(ro + 2)*4u, pk2(hn[6], hn[7]));
            }
            if (sp){                         // t=128 (local col 36)
                float v = fmaxf(accx[oi] + bias, 0.f) + hs[ro + 36];
                hs[ro + 36] = v;
            }
        }
    }

    CLUSTER_SYNC();   // (B) all h_new writes (local + DSMEM halos) visible
}

__global__ void __cluster_dims__(4, 1, 1) __launch_bounds__(NTHREADS, 1)
vgt_kernel(const int* __restrict__ x, const float* __restrict__ emb_w,
           const float* __restrict__ red_w, const float* __restrict__ red_b,
           const float* __restrict__ conv_w, const float* __restrict__ conv_b,
           const float* __restrict__ out_w, const float* __restrict__ out_b,
           float* __restrict__ out)
{
    extern __shared__ __align__(16) float sm[];
    float* ws = sm;                    // 49176 floats (padded weights)
    float* hs = ws + WS_FLOATS;        // 5144
    float* cb = hs + HS_FLOATS;        // 128
    float* m1 = cb + 128;              // 1280
    float* m2 = m1 + 1280;             // 1280  -> total 57008 f = 228032 B

    const int tid = threadIdx.x;
    const int b   = blockIdx.x >> 2;
    const int tg  = blockIdx.x & 3;    // owns t in [tg*32, tg*32+32) (+ t=128 for tg3)

    const uint32_t hs_sh = (uint32_t)__cvta_generic_to_shared(hs);
    const uint32_t lP = (tg > 0) ? mapa32(hs_sh, (uint32_t)(tg - 1)) : 0u;
    const uint32_t rP = (tg < 3) ? mapa32(hs_sh, (uint32_t)(tg + 1)) : 0u;

    // ---- prologue: weights (padded), bias, reducer tables, h0 ----
    for (int idx = tid; idx < NH*3*NH; idx += NTHREADS){
        int o  = idx & 127;
        int ck = idx >> 7;          // = c*3 + k
        int k  = ck % 3;
        int c  = ck / 3;
        ws[idx + (c >> 5)*8] = conv_w[(o*NH + c)*3 + k];
    }
    if (tid < 128) cb[tid] = conv_b[tid];

    for (int idx = tid; idx < 10*NH; idx += NTHREADS){
        int v = idx >> 7;
        int o = idx & 127;
        const float* rw = red_w + o*(2*NH);
        const float* ew = emb_w + v*NH;
        float s1 = 0.f, s2 = 0.f;
        for (int c = 0; c < NH; c++){
            float e = ew[c];
            s1 = fmaf(rw[c],      e, s1);
            s2 = fmaf(rw[NH + c], e, s2);
        }
        m1[idx] = s1;
        m2[idx] = s2;
    }
    for (int idx = tid; idx < HS_FLOATS; idx += NTHREADS) hs[idx] = 0.f;
    __syncthreads();

    // h0 = relu(M1[x[t]] + M2[x[t+128]] + red_b) for local cols [0,40) (incl. halos)
    {
        const int* xb = x + b*256;
        for (int idx = tid; idx < NH*40; idx += NTHREADS){
            int o  = idx / 40;
            int ci = idx - o*40;
            int t  = tg*32 - 4 + ci;
            if (t >= 0 && t < 128){
                int v1 = xb[t];
                int v2 = xb[t + 128];
                float val = m1[v1*NH + o] + m2[v2*NH + o] + red_b[o];
                hs[o*RS + (o >> 5)*8 + ci] = fmaxf(val, 0.f);
            }
        }
    }
    __syncthreads();
    CLUSTER_SYNC();

    // ---- 131 residual conv iterations, h fully smem-resident ----
    #pragma unroll 1
    for (int i = 0; i < 4; i++)  conv_iter<1>(hs, ws, cb, lP, rP, tg);
    #pragma unroll 1
    for (int i = 0; i < 4; i++)  conv_iter<2>(hs, ws, cb, lP, rP, tg);
    #pragma unroll 1
    for (int i = 0; i < NITER - 8; i++) conv_iter<4>(hs, ws, cb, lP, rP, tg);

    // ---- output head: out[b,t,o] = out_w . h[:,t] + out_b, own window ----
    {
        const int tcnt = (tg == 3) ? 33 : 32;
        for (int idx = tid; idx < tcnt*10; idx += NTHREADS){
            int tl = idx / 10;
            int o  = idx % 10;
            int t  = tg*32 + tl;
            int col = 4 + tl;                 // tl==32 -> col 36 == t=128 slot
            const float* wrow = out_w + o*NH;
            float s = out_b[o];
            #pragma unroll 8
            for (int c = 0; c < NH; c++)
                s = fmaf(__ldg(wrow + c), hs[c*RS + (c >> 5)*8 + col], s);
            out[(b*129 + t)*10 + o] = s;
        }
    }
}

extern "C" void kernel_launch(void* const* d_in, const int* in_sizes, int n_in,
                              void* d_out, int out_size)
{
    (void)in_sizes; (void)n_in; (void)out_size;
    const int*   x      = (const int*)  d_in[0];
    const float* emb_w  = (const float*)d_in[1];
    const float* red_w  = (const float*)d_in[2];
    const float* red_b  = (const float*)d_in[3];
    const float* conv_w = (const float*)d_in[4];
    const float* conv_b = (const float*)d_in[5];
    const float* out_w  = (const float*)d_in[6];
    const float* out_b  = (const float*)d_in[7];
    float* out = (float*)d_out;

    const size_t smem = (size_t)(WS_FLOATS + HS_FLOATS + 128 + 2*1280) * sizeof(float); // 228032 B
    cudaFuncSetAttribute(vgt_kernel, cudaFuncAttributeMaxDynamicSharedMemorySize, (int)smem);
    vgt_kernel<<<NB*4, NTHREADS, smem>>>(x, emb_w, red_w, red_b,
                                         conv_w, conv_b, out_w, out_b, out);
}

// round 9
// speedup vs baseline: 1.0008x; 1.0008x over previous
#include <cuda_runtime.h>
#include <cstdint>

#define NB   32
#define NH   128
#define RS   40        // h row: [0,4) L-halo | [4,36) owned 32 | 36 t128/R-halo | ..39
#define CBLK 1288      // 32*RS + 8 pad  (h block stride per 32 channels, floats)
#define WBLK 12296     // 32*384 + 8 pad (w block stride per 32 channels, floats)
#define NITER 131
#define NTHREADS 1024

#define HS_FLOATS (128*RS + 3*8)        // 5144
#define WS_FLOATS (128*384 + 3*8)       // 49176

typedef unsigned long long u64t;

// ---------- packed f32x2 helpers ----------
__device__ __forceinline__ u64t pk2(float a, float b){
    u64t r; asm("mov.b64 %0, {%1, %2};" : "=l"(r) : "f"(a), "f"(b)); return r;
}
__device__ __forceinline__ void fma2(u64t& d, u64t a, u64t b){
    asm("fma.rn.f32x2 %0, %1, %2, %0;" : "+l"(d) : "l"(a), "l"(b));
}
__device__ __forceinline__ void unpk2(u64t v, float& a, float& b){
    asm("mov.b64 {%0, %1}, %2;" : "=f"(a), "=f"(b) : "l"(v));
}
__device__ __forceinline__ float lo2(u64t v){ float a,b; unpk2(v,a,b); return a; }
__device__ __forceinline__ float hi2(u64t v){ float a,b; unpk2(v,a,b); return b; }

__device__ __forceinline__ uint32_t mapa32(uint32_t addr, uint32_t rank){
    uint32_t r; asm("mapa.shared::cluster.u32 %0, %1, %2;" : "=r"(r) : "r"(addr), "r"(rank));
    return r;
}
__device__ __forceinline__ void st_cl_u64(uint32_t addr, u64t v){
    asm volatile("st.shared::cluster.b64 [%0], %1;" :: "r"(addr), "l"(v) : "memory");
}

#define CLUSTER_SYNC() do { \
    asm volatile("barrier.cluster.arrive.aligned;" ::: "memory"); \
    asm volatile("barrier.cluster.wait.aligned;"   ::: "memory"); } while(0)

// One residual dilated-conv iteration; h resident in smem.
// Lanes: og_lo=lane[0:3), ch2=lane[3:5) (4 channel quarters). Warps: oghi=w[0:3), tt=w[3:5).
// Thread: 2 out-ch x 8 t x 32 ch; two shfl.bfly levels (8,16) complete the 128-ch sum in-warp.
template<int D>
__device__ __forceinline__ void conv_iter(
    float* __restrict__ hs, const float* __restrict__ ws, const float* __restrict__ cb,
    uint32_t lP, uint32_t rP, int tg)
{
    const int tid  = threadIdx.x;
    const int lane = tid & 31;
    const int w    = tid >> 5;
    const int og   = ((w & 7) << 3) | (lane & 7);     // 0..63
    const int ch2  = (lane >> 3) & 3;                 // channel quarter
    const int tt   = (w >> 3) & 3;                    // 0..3, t0 = tt*8
    const bool sp  = (tg == 3) && (tt == 3);          // also produce t=128

    u64t acc[2][4] = {{0ull,0ull,0ull,0ull},{0ull,0ull,0ull,0ull}};
    float accx[2] = {0.f, 0.f};

    // window: 16 floats = local cols [tt*8, tt*8+16); owned outputs at window cols [4,12)
    const char*  hb = (const char*)(hs + ch2*CBLK + tt*8);
    const float* wb = ws + ch2*WBLK + og*2;

    #pragma unroll 1
    for (int cc = 0; cc < 32; cc++){
        ulonglong2 a0 = *(const ulonglong2*)(hb);
        ulonglong2 a1 = *(const ulonglong2*)(hb + 16);
        ulonglong2 a2 = *(const ulonglong2*)(hb + 32);
        ulonglong2 a3 = *(const ulonglong2*)(hb + 48);
        float2 w0 = *(const float2*)(wb);
        float2 w1 = *(const float2*)(wb + 128);
        float2 w2 = *(const float2*)(wb + 256);
        u64t u[8] = {a0.x, a0.y, a1.x, a1.y, a2.x, a2.y, a3.x, a3.y};

        if (D != 1){
            constexpr int S0 = (D == 4) ? 0 : 1;
            constexpr int S2 = (D == 4) ? 4 : 3;
            #define DOO(oi, v0, v1, v2) do {                                   \
                u64t d0 = pk2((v0),(v0)), d1 = pk2((v1),(v1)), d2 = pk2((v2),(v2)); \
                fma2(acc[oi][0], d0, u[S0+0]); fma2(acc[oi][1], d0, u[S0+1]);  \
                fma2(acc[oi][2], d0, u[S0+2]); fma2(acc[oi][3], d0, u[S0+3]);  \
                fma2(acc[oi][0], d1, u[2]);    fma2(acc[oi][1], d1, u[3]);     \
                fma2(acc[oi][2], d1, u[4]);    fma2(acc[oi][3], d1, u[5]);     \
                fma2(acc[oi][0], d2, u[S2+0]); fma2(acc[oi][1], d2, u[S2+1]);  \
                fma2(acc[oi][2], d2, u[S2+2]); fma2(acc[oi][3], d2, u[S2+3]);  \
            } while(0)
            DOO(0, w0.x, w1.x, w2.x);
            DOO(1, w0.y, w1.y, w2.y);
            #undef DOO
        } else {
            float s[16];
            #pragma unroll
            for (int j = 0; j < 8; j++) unpk2(u[j], s[2*j], s[2*j+1]);
            u64t om[6];
            #pragma unroll
            for (int j = 1; j < 6; j++) om[j] = pk2(s[2*j+1], s[2*j+2]);
            #define DOO1(oi, v0, v1, v2) do {                                  \
                u64t d0 = pk2((v0),(v0)), d1 = pk2((v1),(v1)), d2 = pk2((v2),(v2)); \
                fma2(acc[oi][0], d0, om[1]); fma2(acc[oi][1], d0, om[2]);      \
                fma2(acc[oi][2], d0, om[3]); fma2(acc[oi][3], d0, om[4]);      \
                fma2(acc[oi][0], d1, u[2]);  fma2(acc[oi][1], d1, u[3]);       \
                fma2(acc[oi][2], d1, u[4]);  fma2(acc[oi][3], d1, u[5]);       \
                fma2(acc[oi][0], d2, om[2]); fma2(acc[oi][1], d2, om[3]);      \
                fma2(acc[oi][2], d2, om[4]); fma2(acc[oi][3], d2, om[5]);      \
            } while(0)
            DOO1(0, w0.x, w1.x, w2.x);
            DOO1(1, w0.y, w1.y, w2.y);
            #undef DOO1
        }

        if (sp){
            // t=128 at window col 12 (local col 36); tap t+D is zero tail
            const float tm = (D == 4) ? lo2(u[4]) : (D == 2 ? lo2(u[5]) : hi2(u[5]));
            const float tz = lo2(u[6]);
            accx[0] = fmaf(w0.x, tm, fmaf(w1.x, tz, accx[0]));
            accx[1] = fmaf(w0.y, tm, fmaf(w1.y, tz, accx[1]));
        }

        hb += RS*4;
        wb += 384;
    }

    // ---- complete 128-channel sums: butterfly over lane bits 3 and 4 ----
    float res[2][8];
    #pragma unroll
    for (int oi = 0; oi < 2; oi++)
        #pragma unroll
        for (int p = 0; p < 4; p++){
            float a, b; unpk2(acc[oi][p], a, b);
            a += __shfl_xor_sync(0xffffffffu, a, 8);
            b += __shfl_xor_sync(0xffffffffu, b, 8);
            a += __shfl_xor_sync(0xffffffffu, a, 16);
            b += __shfl_xor_sync(0xffffffffu, b, 16);
            res[oi][2*p] = a; res[oi][2*p+1] = b;
        }
    if (sp){
        #pragma unroll
        for (int oi = 0; oi < 2; oi++){
            accx[oi] += __shfl_xor_sync(0xffffffffu, accx[oi], 8);
            accx[oi] += __shfl_xor_sync(0xffffffffu, accx[oi], 16);
        }
    }

    CLUSTER_SYNC();   // (A) all reads of h complete cluster-wide

    // ---- epilogue (lanes 0-7): bias + relu + residual; own cols + peer halos ----
    if (ch2 == 0){
        #pragma unroll
        for (int oi = 0; oi < 2; oi++){
            const int   o    = og*2 + oi;
            const int   ro   = o*RS + (o >> 5)*8;
            const float bias = cb[o];
            float* own = hs + ro + 4 + tt*8;
            float hn[8];
            #pragma unroll
            for (int p = 0; p < 8; p++)
                hn[p] = fmaxf(res[oi][p] + bias, 0.f) + own[p];
            *(float4*)own       = make_float4(hn[0], hn[1], hn[2], hn[3]);
            *(float4*)(own + 4) = make_float4(hn[4], hn[5], hn[6], hn[7]);
            if (tt == 0 && tg > 0){          // first 4 owned cols -> left peer R-halo [36,40)
                st_cl_u64(lP + (uint32_t)(ro + 36)*4u, pk2(hn[0], hn[1]));
                st_cl_u64(lP + (uint32_t)(ro + 38)*4u, pk2(hn[2], hn[3]));
            }
            if (tt == 3 && tg < 3){          // last 4 owned cols -> right peer L-halo [0,4)
                st_cl_u64(rP + (uint32_t)(ro + 0)*4u, pk2(hn[4], hn[5]));
                st_cl_u64(rP + (uint32_t)(ro + 2)*4u, pk2(hn[6], hn[7]));
            }
            if (sp){                         // t=128 (local col 36)
                float v = fmaxf(accx[oi] + bias, 0.f) + hs[ro + 36];
                hs[ro + 36] = v;
            }
        }
    }

    CLUSTER_SYNC();   // (B) all h_new writes (local + DSMEM halos) visible
}

__global__ void __cluster_dims__(4, 1, 1) __launch_bounds__(NTHREADS, 1)
vgt_kernel(const int* __restrict__ x, const float* __restrict__ emb_w,
           const float* __restrict__ red_w, const float* __restrict__ red_b,
           const float* __restrict__ conv_w, const float* __restrict__ conv_b,
           const float* __restrict__ out_w, const float* __restrict__ out_b,
           float* __restrict__ out)
{
    extern __shared__ __align__(16) float sm[];
    float* ws = sm;                    // 49176 floats (padded weights)
    float* hs = ws + WS_FLOATS;        // 5144
    float* cb = hs + HS_FLOATS;        // 128
    float* m1 = cb + 128;              // 1280
    float* m2 = m1 + 1280;             // 1280  -> total 57008 f = 228032 B

    const int tid = threadIdx.x;
    const int b   = blockIdx.x >> 2;
    const int tg  = blockIdx.x & 3;    // owns t in [tg*32, tg*32+32) (+ t=128 for tg3)

    const uint32_t hs_sh = (uint32_t)__cvta_generic_to_shared(hs);
    const uint32_t lP = (tg > 0) ? mapa32(hs_sh, (uint32_t)(tg - 1)) : 0u;
    const uint32_t rP = (tg < 3) ? mapa32(hs_sh, (uint32_t)(tg + 1)) : 0u;

    // ---- prologue: weights (padded), bias, reducer tables, h0 ----
    for (int idx = tid; idx < NH*3*NH; idx += NTHREADS){
        int o  = idx & 127;
        int ck = idx >> 7;          // = c*3 + k
        int k  = ck % 3;
        int c  = ck / 3;
        ws[idx + (c >> 5)*8] = conv_w[(o*NH + c)*3 + k];
    }
    if (tid < 128) cb[tid] = conv_b[tid];

    for (int idx = tid; idx < 10*NH; idx += NTHREADS){
        int v = idx >> 7;
        int o = idx & 127;
        const float* rw = red_w + o*(2*NH);
        const float* ew = emb_w + v*NH;
        float s1 = 0.f, s2 = 0.f;
        for (int c = 0; c < NH; c++){
            float e = ew[c];
            s1 = fmaf(rw[c],      e, s1);
            s2 = fmaf(rw[NH + c], e, s2);
        }
        m1[idx] = s1;
        m2[idx] = s2;
    }
    for (int idx = tid; idx < HS_FLOATS; idx += NTHREADS) hs[idx] = 0.f;
    __syncthreads();

    // h0 = relu(M1[x[t]] + M2[x[t+128]] + red_b) for local cols [0,40) (incl. halos)
    {
        const int* xb = x + b*256;
        for (int idx = tid; idx < NH*40; idx += NTHREADS){
            int o  = idx / 40;
            int ci = idx - o*40;
            int t  = tg*32 - 4 + ci;
            if (t >= 0 && t < 128){
                int v1 = xb[t];
                int v2 = xb[t + 128];
                float val = m1[v1*NH + o] + m2[v2*NH + o] + red_b[o];
                hs[o*RS + (o >> 5)*8 + ci] = fmaxf(val, 0.f);
            }
        }
    }
    __syncthreads();
    CLUSTER_SYNC();

    // ---- 131 residual conv iterations, h fully smem-resident ----
    #pragma unroll 1
    for (int i = 0; i < 4; i++)  conv_iter<1>(hs, ws, cb, lP, rP, tg);
    #pragma unroll 1
    for (int i = 0; i < 4; i++)  conv_iter<2>(hs, ws, cb, lP, rP, tg);
    #pragma unroll 1
    for (int i = 0; i < NITER - 8; i++) conv_iter<4>(hs, ws, cb, lP, rP, tg);

    // ---- output head: out[b,t,o] = out_w . h[:,t] + out_b, own window ----
    {
        const int tcnt = (tg == 3) ? 33 : 32;
        for (int idx = tid; idx < tcnt*10; idx += NTHREADS){
            int tl = idx / 10;
            int o  = idx % 10;
            int t  = tg*32 + tl;
            int col = 4 + tl;                 // tl==32 -> col 36 == t=128 slot
            const float* wrow = out_w + o*NH;
            float s = out_b[o];
            #pragma unroll 8
            for (int c = 0; c < NH; c++)
                s = fmaf(__ldg(wrow + c), hs[c*RS + (c >> 5)*8 + col], s);
            out[(b*129 + t)*10 + o] = s;
        }
    }
}

extern "C" void kernel_launch(void* const* d_in, const int* in_sizes, int n_in,
                              void* d_out, int out_size)
{
    (void)in_sizes; (void)n_in; (void)out_size;
    const int*   x      = (const int*)  d_in[0];
    const float* emb_w  = (const float*)d_in[1];
    const float* red_w  = (const float*)d_in[2];
    const float* red_b  = (const float*)d_in[3];
    const float* conv_w = (const float*)d_in[4];
    const float* conv_b = (const float*)d_in[5];
    const float* out_w  = (const float*)d_in[6];
    const float* out_b  = (const float*)d_in[7];
    float* out = (float*)d_out;

    const size_t smem = (size_t)(WS_FLOATS + HS_FLOATS + 128 + 2*1280) * sizeof(float); // 228032 B
    cudaFuncSetAttribute(vgt_kernel, cudaFuncAttributeMaxDynamicSharedMemorySize, (int)smem);
    vgt_kernel<<<NB*4, NTHREADS, smem>>>(x, emb_w, red_w, red_b,
                                         conv_w, conv_b, out_w, out_b, out);
}

// round 11
// speedup vs baseline: 1.0846x; 1.0837x over previous
#include <cuda_runtime.h>
#include <cstdint>

#define NB   32
#define NH   128
#define RS   40        // h row: [0,4) L-halo | [4,36) owned 32 | 36 t128/R-halo | 37..39
#define CBLK 1288      // 32*RS + 8   (h quarter stride, ≡8 mod 32 banks)
#define WBLK 12304     // 32*384 + 16 (w quarter stride, ≡16 mod 32 banks)
#define NITER 131
#define NTHREADS 512

#define WS_FLOATS (4*WBLK)   // 49216
#define HS_FLOATS (4*CBLK)   // 5152

// ---------- cluster helpers ----------
__device__ __forceinline__ uint32_t mapa32(uint32_t addr, uint32_t rank){
    uint32_t r; asm("mapa.shared::cluster.u32 %0, %1, %2;" : "=r"(r) : "r"(addr), "r"(rank));
    return r;
}
__device__ __forceinline__ void st_cl_u64(uint32_t addr, float a, float b){
    unsigned long long v;
    asm("mov.b64 %0, {%1, %2};" : "=l"(v) : "f"(a), "f"(b));
    asm volatile("st.shared::cluster.b64 [%0], %1;" :: "r"(addr), "l"(v) : "memory");
}
#define CLUSTER_SYNC() do { \
    asm volatile("barrier.cluster.arrive.aligned;" ::: "memory"); \
    asm volatile("barrier.cluster.wait.aligned;"   ::: "memory"); } while(0)

// One residual dilated-conv iteration; h resident in smem, SCALAR FFMA inner loop.
// Lanes: og_lo=lane[0:3), q=lane[3:5) (channel quarter). Warps: oghi=w[0:3), tt=w[3].
// Thread: 2 out-ch (o=og*2+{0,1}) x 16 t (t0=tt*16) x 32 ch (quarter q);
// two shfl.bfly levels (8,16) complete the 128-channel sum in-warp.
template<int D>
__device__ __forceinline__ void conv_iter(
    float* __restrict__ hs, const float* __restrict__ ws, const float* __restrict__ cb,
    uint32_t lP, uint32_t rP, int tg)
{
    const int tid  = threadIdx.x;
    const int lane = tid & 31;
    const int w    = tid >> 5;
    const int og   = ((w & 7) << 3) | (lane & 7);    // 0..63
    const int q    = (lane >> 3) & 3;                // channel quarter
    const int tt   = (w >> 3) & 1;                   // t half: t0 = tt*16
    const bool sp  = (tg == 3) && (tt == 1);         // also produce t=128

    float acc[2][16];
    #pragma unroll
    for (int oi = 0; oi < 2; oi++)
        #pragma unroll
        for (int p = 0; p < 16; p++) acc[oi][p] = 0.f;
    float accx[2] = {0.f, 0.f};

    // window: 24 floats = local cols [tt*16, tt*16+24); owned outputs at window idx [4,20)
    const float* hb = hs + q*CBLK + tt*16;
    const float* wb = ws + q*WBLK + og*2;

    #pragma unroll 1
    for (int cc = 0; cc < 32; cc++){
        float4 f0 = ((const float4*)hb)[0];
        float4 f1 = ((const float4*)hb)[1];
        float4 f2 = ((const float4*)hb)[2];
        float4 f3 = ((const float4*)hb)[3];
        float4 f4 = ((const float4*)hb)[4];
        float4 f5 = ((const float4*)hb)[5];
        float2 w0 = *(const float2*)(wb);
        float2 w1 = *(const float2*)(wb + 128);
        float2 w2 = *(const float2*)(wb + 256);
        const float s[24] = {f0.x,f0.y,f0.z,f0.w, f1.x,f1.y,f1.z,f1.w,
                             f2.x,f2.y,f2.z,f2.w, f3.x,f3.y,f3.z,f3.w,
                             f4.x,f4.y,f4.z,f4.w, f5.x,f5.y,f5.z,f5.w};

        #pragma unroll
        for (int p = 0; p < 16; p++){
            acc[0][p] = fmaf(w0.x, s[p + 4 - D], acc[0][p]);
            acc[0][p] = fmaf(w1.x, s[p + 4],     acc[0][p]);
            acc[0][p] = fmaf(w2.x, s[p + 4 + D], acc[0][p]);
            acc[1][p] = fmaf(w0.y, s[p + 4 - D], acc[1][p]);
            acc[1][p] = fmaf(w1.y, s[p + 4],     acc[1][p]);
            acc[1][p] = fmaf(w2.y, s[p + 4 + D], acc[1][p]);
        }
        if (sp){
            // t=128 at window idx 20 (local col 36); tap t+D is zero tail
            accx[0] = fmaf(w0.x, s[20 - D], fmaf(w1.x, s[20], accx[0]));
            accx[1] = fmaf(w0.y, s[20 - D], fmaf(w1.y, s[20], accx[1]));
        }

        hb += RS;
        wb += 384;
    }

    // ---- complete 128-channel sums: butterfly over lane bits 3,4 ----
    #pragma unroll
    for (int oi = 0; oi < 2; oi++)
        #pragma unroll
        for (int p = 0; p < 16; p++){
            float a = acc[oi][p];
            a += __shfl_xor_sync(0xffffffffu, a, 8);
            a += __shfl_xor_sync(0xffffffffu, a, 16);
            acc[oi][p] = a;
        }
    if (sp){
        #pragma unroll
        for (int oi = 0; oi < 2; oi++){
            accx[oi] += __shfl_xor_sync(0xffffffffu, accx[oi], 8);
            accx[oi] += __shfl_xor_sync(0xffffffffu, accx[oi], 16);
        }
    }

    CLUSTER_SYNC();   // (A) all reads of h complete cluster-wide

    // ---- epilogue (q==0 lanes): bias + relu + residual; own cols + peer halos ----
    if (q == 0){
        #pragma unroll
        for (int oi = 0; oi < 2; oi++){
            const int   o    = og*2 + oi;
            const int   ro   = (o >> 5)*CBLK + (o & 31)*RS;
            const float bias = cb[o];
            float* own = hs + ro + 4 + tt*16;
            float hn[16];
            #pragma unroll
            for (int p4 = 0; p4 < 4; p4++){
                float4 h4 = ((const float4*)own)[p4];
                hn[4*p4+0] = fmaxf(acc[oi][4*p4+0] + bias, 0.f) + h4.x;
                hn[4*p4+1] = fmaxf(acc[oi][4*p4+1] + bias, 0.f) + h4.y;
                hn[4*p4+2] = fmaxf(acc[oi][4*p4+2] + bias, 0.f) + h4.z;
                hn[4*p4+3] = fmaxf(acc[oi][4*p4+3] + bias, 0.f) + h4.w;
                ((float4*)own)[p4] = make_float4(hn[4*p4+0], hn[4*p4+1], hn[4*p4+2], hn[4*p4+3]);
            }
            if (tt == 0 && tg > 0){   // my t 0..3 -> left peer R-halo cols [36,40)
                st_cl_u64(lP + (uint32_t)(ro + 36)*4u, hn[0], hn[1]);
                st_cl_u64(lP + (uint32_t)(ro + 38)*4u, hn[2], hn[3]);
            }
            if (tt == 1 && tg < 3){   // my t 28..31 -> right peer L-halo cols [0,4)
                st_cl_u64(rP + (uint32_t)(ro + 0)*4u, hn[12], hn[13]);
                st_cl_u64(rP + (uint32_t)(ro + 2)*4u, hn[14], hn[15]);
            }
            if (sp){                  // t=128 (local col 36)
                float v = fmaxf(accx[oi] + bias, 0.f) + hs[ro + 36];
                hs[ro + 36] = v;
            }
        }
    }

    CLUSTER_SYNC();   // (B) all h_new writes (local + DSMEM halos) visible
}

__global__ void __cluster_dims__(4, 1, 1) __launch_bounds__(NTHREADS, 1)
vgt_kernel(const int* __restrict__ x, const float* __restrict__ emb_w,
           const float* __restrict__ red_w, const float* __restrict__ red_b,
           const float* __restrict__ conv_w, const float* __restrict__ conv_b,
           const float* __restrict__ out_w, const float* __restrict__ out_b,
           float* __restrict__ out)
{
    extern __shared__ __align__(16) float sm[];
    float* ws = sm;                    // 49216 floats
    float* hs = ws + WS_FLOATS;        // 5152
    float* cb = hs + HS_FLOATS;        // 128
    float* m1 = cb + 128;              // 1280
    float* m2 = m1 + 1280;             // 1280  -> total 57056 f = 228224 B

    const int tid = threadIdx.x;
    const int b   = blockIdx.x >> 2;
    const int tg  = blockIdx.x & 3;    // owns t in [tg*32, tg*32+32) (+ t=128 for tg3)

    const uint32_t hs_sh = (uint32_t)__cvta_generic_to_shared(hs);
    const uint32_t lP = (tg > 0) ? mapa32(hs_sh, (uint32_t)(tg - 1)) : 0u;
    const uint32_t rP = (tg < 3) ? mapa32(hs_sh, (uint32_t)(tg + 1)) : 0u;

    // ---- prologue: weights (quartered layout), bias, reducer tables, h0 ----
    for (int idx = tid; idx < 3*NH*NH; idx += NTHREADS){
        int k = idx % 3;
        int r = idx / 3;             // = o*128 + c
        int o = r >> 7;
        int c = r & 127;
        ws[(c >> 5)*WBLK + ((c & 31)*3 + k)*128 + o] = conv_w[idx];
    }
    if (tid < 128) cb[tid] = conv_b[tid];

    for (int idx = tid; idx < 10*NH; idx += NTHREADS){
        int v = idx >> 7, o = idx & 127;
        const float* rw = red_w + o*(2*NH);
        const float* ew = emb_w + v*NH;
        float s1 = 0.f, s2 = 0.f;
        for (int c = 0; c < NH; c++){
            float e = ew[c];
            s1 = fmaf(rw[c],      e, s1);
            s2 = fmaf(rw[NH + c], e, s2);
        }
        m1[idx] = s1;
        m2[idx] = s2;
    }
    for (int idx = tid; idx < HS_FLOATS; idx += NTHREADS) hs[idx] = 0.f;
    __syncthreads();

    // h0 = relu(M1[x[t]] + M2[x[t+128]] + red_b) for local cols [0,40) (incl. halos)
    {
        const int* xb = x + b*256;
        for (int idx = tid; idx < NH*40; idx += NTHREADS){
            int c  = idx / 40;
            int ci = idx - c*40;
            int t  = tg*32 - 4 + ci;
            if (t >= 0 && t < 128){
                float val = m1[xb[t]*NH + c] + m2[xb[t + 128]*NH + c] + red_b[c];
                hs[(c >> 5)*CBLK + (c & 31)*RS + ci] = fmaxf(val, 0.f);
            }
        }
    }
    __syncthreads();
    CLUSTER_SYNC();

    // ---- 131 residual conv iterations, h fully smem-resident ----
    #pragma unroll 1
    for (int i = 0; i < 4; i++)  conv_iter<1>(hs, ws, cb, lP, rP, tg);
    #pragma unroll 1
    for (int i = 0; i < 4; i++)  conv_iter<2>(hs, ws, cb, lP, rP, tg);
    #pragma unroll 1
    for (int i = 0; i < NITER - 8; i++) conv_iter<4>(hs, ws, cb, lP, rP, tg);

    // ---- output head: out[b,t,o] = out_w . h[:,t] + out_b, own window ----
    {
        const int tcnt = (tg == 3) ? 33 : 32;
        for (int idx = tid; idx < tcnt*10; idx += NTHREADS){
            int tl = idx / 10;
            int o  = idx % 10;
            int t  = tg*32 + tl;
            int col = 4 + tl;                 // tl==32 -> col 36 == t=128 slot
            const float* wrow = out_w + o*NH;
            float s = out_b[o];
            #pragma unroll 8
            for (int c = 0; c < NH; c++)
                s = fmaf(__ldg(wrow + c), hs[(c >> 5)*CBLK + (c & 31)*RS + col], s);
            out[(b*129 + t)*10 + o] = s;
        }
    }
}

extern "C" void kernel_launch(void* const* d_in, const int* in_sizes, int n_in,
                              void* d_out, int out_size)
{
    (void)in_sizes; (void)n_in; (void)out_size;
    const int*   x      = (const int*)  d_in[0];
    const float* emb_w  = (const float*)d_in[1];
    const float* red_w  = (const float*)d_in[2];
    const float* red_b  = (const float*)d_in[3];
    const float* conv_w = (const float*)d_in[4];
    const float* conv_b = (const float*)d_in[5];
    const float* out_w  = (const float*)d_in[6];
    const float* out_b  = (const float*)d_in[7];
    float* out = (float*)d_out;

    const size_t smem = (size_t)(WS_FLOATS + HS_FLOATS + 128 + 2*1280) * sizeof(float); // 228224 B
    cudaFuncSetAttribute(vgt_kernel, cudaFuncAttributeMaxDynamicSharedMemorySize, (int)smem);
    vgt_kernel<<<NB*4, NTHREADS, smem>>>(x, emb_w, red_w, red_b,
                                         conv_w, conv_b, out_w, out_b, out);
}

// round 13
// speedup vs baseline: 1.0986x; 1.0129x over previous
#include <cuda_runtime.h>
#include <cstdint>

#define NB   32
#define NH   128
#define RS   40          // h row: [0,4) L-halo | [4,36) owned 32 | 36 t128/R-halo | 37..39
#define CBLK 1288        // 32*RS + 8   (h quarter stride, ≡8 mod 32 banks)
#define WBLK 12304       // 32*384 + 16 (w quarter stride, ≡16 mod 32 banks)
#define NITER 131
#define NTHREADS 1024

#define WS_FLOATS (4*WBLK)   // 49216
#define HS_FLOATS (4*CBLK)   // 5152

typedef unsigned long long u64t;

// ---------- packed f32x2 helpers ----------
__device__ __forceinline__ u64t pk2(float a, float b){
    u64t r; asm("mov.b64 %0, {%1, %2};" : "=l"(r) : "f"(a), "f"(b)); return r;
}
__device__ __forceinline__ void fma2(u64t& d, u64t a, u64t b){
    asm("fma.rn.f32x2 %0, %1, %2, %0;" : "+l"(d) : "l"(a), "l"(b));
}
__device__ __forceinline__ void unpk2(u64t v, float& a, float& b){
    asm("mov.b64 {%0, %1}, %2;" : "=f"(a), "=f"(b) : "l"(v));
}
__device__ __forceinline__ float lo2(u64t v){ float a,b; unpk2(v,a,b); return a; }
__device__ __forceinline__ float hi2(u64t v){ float a,b; unpk2(v,a,b); return b; }

__device__ __forceinline__ uint32_t mapa32(uint32_t addr, uint32_t rank){
    uint32_t r; asm("mapa.shared::cluster.u32 %0, %1, %2;" : "=r"(r) : "r"(addr), "r"(rank));
    return r;
}
__device__ __forceinline__ void st_cl_u64(uint32_t addr, float a, float b){
    u64t v; asm("mov.b64 %0, {%1, %2};" : "=l"(v) : "f"(a), "f"(b));
    asm volatile("st.shared::cluster.b64 [%0], %1;" :: "r"(addr), "l"(v) : "memory");
}
#define CLUSTER_SYNC() do { \
    asm volatile("barrier.cluster.arrive.aligned;" ::: "memory"); \
    asm volatile("barrier.cluster.wait.aligned;"   ::: "memory"); } while(0)

// One residual dilated-conv iteration; h resident in smem (single buffer, in-place).
// Warps: oghi=w[0:3), tt=w[3:5). Lanes: og_lo=lane[0:3), q=lane[3:5) (channel quarter).
// Thread: 2 out-ch x 8 t x 32 ch; shfl.bfly(8,16) completes the 128-channel sum in-warp.
template<int D>
__device__ __forceinline__ void conv_iter(
    float* __restrict__ hs, const float* __restrict__ ws, const float* __restrict__ cb,
    uint32_t lP, uint32_t rP, int tg)
{
    const int tid   = threadIdx.x;
    const int lane  = tid & 31;
    const int w     = tid >> 5;
    const int og_lo = lane & 7;
    const int q     = (lane >> 3) & 3;
    const int oghi  = w & 7;
    const int tt    = (w >> 3) & 3;
    const int t0    = tt * 8;
    const int og    = oghi*8 + og_lo;            // 0..63
    const bool sp   = (tg == 3) && (tt == 3);    // also produce t=128 (local col 36)

    u64t acc[2][4] = {{0ull,0ull,0ull,0ull},{0ull,0ull,0ull,0ull}};
    float accx[2] = {0.f, 0.f};

    // window: 16 floats = local cols [t0, t0+16); owned outputs at window idx [4,12)
    const char*  hb = (const char*)(hs + q*CBLK) + t0*4;
    const float* wb = ws + q*WBLK + og*2;

    #pragma unroll 1
    for (int cc = 0; cc < 32; cc++){
        ulonglong2 a0 = *(const ulonglong2*)(hb);
        ulonglong2 a1 = *(const ulonglong2*)(hb + 16);
        ulonglong2 a2 = *(const ulonglong2*)(hb + 32);
        ulonglong2 a3 = *(const ulonglong2*)(hb + 48);
        float2 w0 = *(const float2*)(wb);
        float2 w1 = *(const float2*)(wb + 128);
        float2 w2 = *(const float2*)(wb + 256);
        u64t u[8] = {a0.x, a0.y, a1.x, a1.y, a2.x, a2.y, a3.x, a3.y};

        if (D != 1){
            constexpr int S0 = (D == 4) ? 0 : 1;
            constexpr int S2 = (D == 4) ? 4 : 3;
            #define DOO(oi, v0, v1, v2) do {                                   \
                u64t d0 = pk2((v0),(v0)), d1 = pk2((v1),(v1)), d2 = pk2((v2),(v2)); \
                fma2(acc[oi][0], d0, u[S0+0]); fma2(acc[oi][1], d0, u[S0+1]);  \
                fma2(acc[oi][2], d0, u[S0+2]); fma2(acc[oi][3], d0, u[S0+3]);  \
                fma2(acc[oi][0], d1, u[2]);    fma2(acc[oi][1], d1, u[3]);     \
                fma2(acc[oi][2], d1, u[4]);    fma2(acc[oi][3], d1, u[5]);     \
                fma2(acc[oi][0], d2, u[S2+0]); fma2(acc[oi][1], d2, u[S2+1]);  \
                fma2(acc[oi][2], d2, u[S2+2]); fma2(acc[oi][3], d2, u[S2+3]);  \
            } while(0)
            DOO(0, w0.x, w1.x, w2.x);
            DOO(1, w0.y, w1.y, w2.y);
            #undef DOO
        } else {
            float s[16];
            #pragma unroll
            for (int j = 0; j < 8; j++) unpk2(u[j], s[2*j], s[2*j+1]);
            u64t om[6];
            #pragma unroll
            for (int j = 1; j < 6; j++) om[j] = pk2(s[2*j+1], s[2*j+2]);
            #define DOO1(oi, v0, v1, v2) do {                                  \
                u64t d0 = pk2((v0),(v0)), d1 = pk2((v1),(v1)), d2 = pk2((v2),(v2)); \
                fma2(acc[oi][0], d0, om[1]); fma2(acc[oi][1], d0, om[2]);      \
                fma2(acc[oi][2], d0, om[3]); fma2(acc[oi][3], d0, om[4]);      \
                fma2(acc[oi][0], d1, u[2]);  fma2(acc[oi][1], d1, u[3]);       \
                fma2(acc[oi][2], d1, u[4]);  fma2(acc[oi][3], d1, u[5]);       \
                fma2(acc[oi][0], d2, om[2]); fma2(acc[oi][1], d2, om[3]);      \
                fma2(acc[oi][2], d2, om[4]); fma2(acc[oi][3], d2, om[5]);      \
            } while(0)
            DOO1(0, w0.x, w1.x, w2.x);
            DOO1(1, w0.y, w1.y, w2.y);
            #undef DOO1
        }

        if (sp){
            // t=128 at window idx 12 (col 36); tap t-D at idx 12-D; tap t+D is zero tail
            const float tm = (D == 4) ? lo2(u[4]) : (D == 2 ? lo2(u[5]) : hi2(u[5]));
            const float tz = lo2(u[6]);
            accx[0] = fmaf(w0.x, tm, fmaf(w1.x, tz, accx[0]));
            accx[1] = fmaf(w0.y, tm, fmaf(w1.y, tz, accx[1]));
        }

        hb += RS*4;
        wb += 384;
    }

    // ---- complete 128-channel sums: butterfly over lane bits 3,4 ----
    float res[2][8];
    #pragma unroll
    for (int oi = 0; oi < 2; oi++)
        #pragma unroll
        for (int p = 0; p < 4; p++){
            float a, b; unpk2(acc[oi][p], a, b);
            a += __shfl_xor_sync(0xffffffffu, a, 8);
            b += __shfl_xor_sync(0xffffffffu, b, 8);
            a += __shfl_xor_sync(0xffffffffu, a, 16);
            b += __shfl_xor_sync(0xffffffffu, b, 16);
            res[oi][2*p] = a; res[oi][2*p+1] = b;
        }
    if (sp){
        #pragma unroll
        for (int oi = 0; oi < 2; oi++){
            accx[oi] += __shfl_xor_sync(0xffffffffu, accx[oi], 8);
            accx[oi] += __shfl_xor_sync(0xffffffffu, accx[oi], 16);
        }
    }

    CLUSTER_SYNC();   // (A) all reads of h complete cluster-wide

    // ---- epilogue (q==0 lanes): bias + relu + residual in place + peer halos ----
    if (q == 0){
        #pragma unroll
        for (int oi = 0; oi < 2; oi++){
            const int   o    = og*2 + oi;
            const int   ro   = (o >> 5)*CBLK + (o & 31)*RS;
            const float bias = cb[o];
            float* own = hs + ro + 4 + t0;
            float hn[8];
            float4 h0 = ((const float4*)own)[0];
            float4 h1 = ((const float4*)own)[1];
            hn[0] = fmaxf(res[oi][0] + bias, 0.f) + h0.x;
            hn[1] = fmaxf(res[oi][1] + bias, 0.f) + h0.y;
            hn[2] = fmaxf(res[oi][2] + bias, 0.f) + h0.z;
            hn[3] = fmaxf(res[oi][3] + bias, 0.f) + h0.w;
            hn[4] = fmaxf(res[oi][4] + bias, 0.f) + h1.x;
            hn[5] = fmaxf(res[oi][5] + bias, 0.f) + h1.y;
            hn[6] = fmaxf(res[oi][6] + bias, 0.f) + h1.z;
            hn[7] = fmaxf(res[oi][7] + bias, 0.f) + h1.w;
            ((float4*)own)[0] = make_float4(hn[0], hn[1], hn[2], hn[3]);
            ((float4*)own)[1] = make_float4(hn[4], hn[5], hn[6], hn[7]);
            if (tt == 0 && tg > 0){   // my t 0..3 -> left peer R-halo cols [36,40)
                st_cl_u64(lP + (uint32_t)(ro + 36)*4u, hn[0], hn[1]);
                st_cl_u64(lP + (uint32_t)(ro + 38)*4u, hn[2], hn[3]);
            }
            if (tt == 3 && tg < 3){   // my t 28..31 (cols [32,36)) -> right peer L-halo [0,4)
                st_cl_u64(rP + (uint32_t)(ro + 0)*4u, hn[4], hn[5]);
                st_cl_u64(rP + (uint32_t)(ro + 2)*4u, hn[6], hn[7]);
            }
            if (sp){                  // t=128 (local col 36), tg3 only
                hs[ro + 36] = fmaxf(accx[oi] + bias, 0.f) + hs[ro + 36];
            }
        }
    }

    CLUSTER_SYNC();   // (B) all new-h writes (local + DSMEM halos) visible
}

__global__ void __cluster_dims__(4, 1, 1) __launch_bounds__(NTHREADS, 1)
vgt_kernel(const int* __restrict__ x, const float* __restrict__ emb_w,
           const float* __restrict__ red_w, const float* __restrict__ red_b,
           const float* __restrict__ conv_w, const float* __restrict__ conv_b,
           const float* __restrict__ out_w, const float* __restrict__ out_b,
           float* __restrict__ out)
{
    extern __shared__ __align__(16) float sm[];
    float* ws = sm;                    // 49216 floats (quartered weights)
    float* hs = ws + WS_FLOATS;        // 5152
    float* cb = hs + HS_FLOATS;        // 128
    float* m1 = cb + 128;              // 1280
    float* m2 = m1 + 1280;             // 1280  -> total 57056 f = 228224 B

    const int tid = threadIdx.x;
    const int b   = blockIdx.x >> 2;
    const int tg  = blockIdx.x & 3;    // owns t in [tg*32, tg*32+32) (+ t=128 for tg3)

    const uint32_t hs_sh = (uint32_t)__cvta_generic_to_shared(hs);
    const uint32_t lP = (tg > 0) ? mapa32(hs_sh, (uint32_t)(tg - 1)) : 0u;
    const uint32_t rP = (tg < 3) ? mapa32(hs_sh, (uint32_t)(tg + 1)) : 0u;

    // ---- prologue: weights (quartered, bijective scatter), bias, tables, h0 ----
    for (int idx = tid; idx < 3*NH*NH; idx += NTHREADS){
        int k = idx % 3;
        int r = idx / 3;             // = o*128 + c
        int o = r >> 7;
        int c = r & 127;
        ws[(c >> 5)*WBLK + ((c & 31)*3 + k)*128 + o] = conv_w[idx];
    }
    if (tid < 128) cb[tid] = conv_b[tid];

    for (int idx = tid; idx < 10*NH; idx += NTHREADS){
        int v = idx >> 7, o = idx & 127;
        const float* rw = red_w + o*(2*NH);
        const float* ew = emb_w + v*NH;
        float s1 = 0.f, s2 = 0.f;
        for (int c = 0; c < NH; c++){
            float e = ew[c];
            s1 = fmaf(rw[c],      e, s1);
            s2 = fmaf(rw[NH + c], e, s2);
        }
        m1[idx] = s1;
        m2[idx] = s2;
    }
    for (int idx = tid; idx < HS_FLOATS; idx += NTHREADS) hs[idx] = 0.f;
    __syncthreads();

    // h0 = relu(M1[x[t]] + M2[x[t+128]] + red_b) for local cols [0,40) (incl. halos)
    {
        const int* xb = x + b*256;
        for (int idx = tid; idx < NH*40; idx += NTHREADS){
            int c  = idx / 40;
            int ci = idx - c*40;
            int t  = tg*32 - 4 + ci;
            if (t >= 0 && t < 128){
                float val = m1[xb[t]*NH + c] + m2[xb[t + 128]*NH + c] + red_b[c];
                hs[(c >> 5)*CBLK + (c & 31)*RS + ci] = fmaxf(val, 0.f);
            }
        }
    }
    __syncthreads();
    CLUSTER_SYNC();

    // ---- 131 residual conv iterations, h fully smem-resident ----
    #pragma unroll 1
    for (int i = 0; i < 4; i++)  conv_iter<1>(hs, ws, cb, lP, rP, tg);
    #pragma unroll 1
    for (int i = 0; i < 4; i++)  conv_iter<2>(hs, ws, cb, lP, rP, tg);
    #pragma unroll 1
    for (int i = 0; i < NITER - 8; i++) conv_iter<4>(hs, ws, cb, lP, rP, tg);

    // ---- output head: out[b,t,o] = out_w . h[:,t] + out_b, own window ----
    {
        const int tcnt = (tg == 3) ? 33 : 32;
        for (int idx = tid; idx < tcnt*10; idx += NTHREADS){
            int tl = idx / 10;
            int o  = idx % 10;
            int t  = tg*32 + tl;
            int col = 4 + tl;                 // tl==32 -> col 36 == t=128 slot
            const float* wrow = out_w + o*NH;
            float s = out_b[o];
            #pragma unroll 8
            for (int c = 0; c < NH; c++)
                s = fmaf(__ldg(wrow + c), hs[(c >> 5)*CBLK + (c & 31)*RS + col], s);
            out[(b*129 + t)*10 + o] = s;
        }
    }
}

extern "C" void kernel_launch(void* const* d_in, const int* in_sizes, int n_in,
                              void* d_out, int out_size)
{
    (void)in_sizes; (void)n_in; (void)out_size;
    const int*   x      = (const int*)  d_in[0];
    const float* emb_w  = (const float*)d_in[1];
    const float* red_w  = (const float*)d_in[2];
    const float* red_b  = (const float*)d_in[3];
    const float* conv_w = (const float*)d_in[4];
    const float* conv_b = (const float*)d_in[5];
    const float* out_w  = (const float*)d_in[6];
    const float* out_b  = (const float*)d_in[7];
    float* out = (float*)d_out;

    const size_t smem = (size_t)(WS_FLOATS + HS_FLOATS + 128 + 2*1280) * sizeof(float); // 228224 B
    cudaFuncSetAttribute(vgt_kernel, cudaFuncAttributeMaxDynamicSharedMemorySize, (int)smem);
    vgt_kernel<<<NB*4, NTHREADS, smem>>>(x, emb_w, red_w, red_b,
                                         conv_w, conv_b, out_w, out_b, out);
}

// round 14
// speedup vs baseline: 2.3923x; 2.1776x over previous
#include <cuda_runtime.h>
#include <cuda_fp16.h>
#include <cstdint>

#define NB 32
#define NITER 131
#define NTHREADS 1024

// ---- smem float offsets ----
#define WSH_F   0        // 3*128*136 halfs = 26112 floats (A: W taps, fp16, padded rows)
#define HH_F    26112    // 128*56 halfs = 3584 floats     (B: H fp16 [c][r], padded rows)
#define HM_F    29696    // 128*49 floats                  (master H fp32 [c][r])
#define P_F     35968    // 3*128*50 floats = 19200        (tap products, fp32)
#define CB_F    55168    // 128 floats (conv bias)
#define SM_F    55296    // total floats = 221184 B

#define WS1B    34816    // bytes per W tap   (128*136*2)
#define HH_STRH 56       // halfs per Hh row  (112 B = 7*16B, ldmatrix conflict-free)
#define HM_STR  49       // floats per Hm row (odd -> bank-clean)
#define P_STR   50       // floats per P row  (even -> 8B-aligned frag stores)
#define P_TAP   6400     // floats per P tap

// ---------- cluster / mma helpers ----------
__device__ __forceinline__ uint32_t mapa32(uint32_t addr, uint32_t rank){
    uint32_t r; asm("mapa.shared::cluster.u32 %0, %1, %2;" : "=r"(r) : "r"(addr), "r"(rank));
    return r;
}
__device__ __forceinline__ void st_cl_f32(uint32_t addr, float v){
    asm volatile("st.shared::cluster.f32 [%0], %1;" :: "r"(addr), "f"(v) : "memory");
}
#define CLUSTER_SYNC() do { \
    asm volatile("barrier.cluster.arrive.aligned;" ::: "memory"); \
    asm volatile("barrier.cluster.wait.aligned;"   ::: "memory"); } while(0)

__device__ __forceinline__ void ldmA(uint32_t* a, uint32_t addr){
    asm volatile("ldmatrix.sync.aligned.m8n8.x4.shared.b16 {%0,%1,%2,%3}, [%4];"
        : "=r"(a[0]), "=r"(a[1]), "=r"(a[2]), "=r"(a[3]) : "r"(addr));
}
__device__ __forceinline__ void ldmBT(uint32_t* b, uint32_t addr){
    asm volatile("ldmatrix.sync.aligned.m8n8.x2.trans.shared.b16 {%0,%1}, [%2];"
        : "=r"(b[0]), "=r"(b[1]) : "r"(addr));
}
__device__ __forceinline__ void mma16816(float* d, const uint32_t* a, const uint32_t* b){
    asm volatile("mma.sync.aligned.m16n8k16.row.col.f32.f16.f16.f32 "
        "{%0,%1,%2,%3},{%4,%5,%6,%7},{%8,%9},{%0,%1,%2,%3};"
        : "+f"(d[0]), "+f"(d[1]), "+f"(d[2]), "+f"(d[3])
        : "r"(a[0]), "r"(a[1]), "r"(a[2]), "r"(a[3]), "r"(b[0]), "r"(b[1]));
}

// One residual dilated-conv iteration.
// Phase 1: refresh fp16 halo cols from fp32 master (peer DSMEM wrote f32 only).
// Phase 2: 24 warps GEMM  P_k[o, r] = sum_c W_k[o,c] * Hh[c, r]   (no shifts).
// Phase 3: combine with dilation shifts, relu+residual in fp32, halo push (f32).
template<int D>
__device__ __forceinline__ void do_iter(float* sm, uint32_t smS,
                                        uint32_t lPm, uint32_t rPm, int tg)
{
    const int tid  = threadIdx.x;
    const int lane = tid & 31;
    const int w    = tid >> 5;
    __half* Hh = (__half*)(sm + HH_F);
    float*  Hm = sm + HM_F;
    float*  P  = sm + P_F;
    const float* cb = sm + CB_F;

    // ---- phase 1: fp16 halo refresh (cols 0..3 and 36..39, all 128 c) ----
    {
        const int c  = tid >> 3;
        const int rr = tid & 7;
        const int r  = (rr < 4) ? rr : (32 + rr);
        Hh[c*HH_STRH + r] = __float2half_rn(Hm[c*HM_STR + r]);
    }
    __syncthreads();

    // ---- phase 2: GEMM (warps 0..23): m-tile = w/3, n-pair = w%3 ----
    if (w < 24){
        const int m0 = (w/3) << 4;
        const int n0 = (w%3) << 4;
        const uint32_t aBase = smS + (uint32_t)((m0 + (lane & 15))*136*2) + ((lane >> 4) << 4);
        const uint32_t bBase = smS + (uint32_t)(HH_F*4) + (uint32_t)((lane & 15)*112) + (n0 << 1);

        float d[3][2][4];
        #pragma unroll
        for (int t = 0; t < 3; t++)
            #pragma unroll
            for (int nt = 0; nt < 2; nt++)
                #pragma unroll
                for (int j = 0; j < 4; j++) d[t][nt][j] = 0.f;

        #pragma unroll
        for (int k0 = 0; k0 < 128; k0 += 16){
            uint32_t b0[2], b1[2], a[4];
            ldmBT(b0, bBase + (uint32_t)(k0*112));
            ldmBT(b1, bBase + (uint32_t)(k0*112) + 16u);
            #pragma unroll
            for (int tap = 0; tap < 3; tap++){
                ldmA(a, aBase + (uint32_t)(tap*WS1B) + ((uint32_t)k0 << 1));
                mma16816(d[tap][0], a, b0);
                mma16816(d[tap][1], a, b1);
            }
        }
        const int prow = m0 + (lane >> 2);
        const int pcol = n0 + ((lane & 3) << 1);
        #pragma unroll
        for (int tap = 0; tap < 3; tap++)
            #pragma unroll
            for (int nt = 0; nt < 2; nt++){
                float* pp = P + tap*P_TAP + prow*P_STR + pcol + nt*8;
                *(float2*)pp              = make_float2(d[tap][nt][0], d[tap][nt][1]);
                *(float2*)(pp + 8*P_STR)  = make_float2(d[tap][nt][2], d[tap][nt][3]);
            }
    }
    CLUSTER_SYNC();   // P visible; all CTAs' GEMM reads of their Hh complete

    // ---- phase 3: combine + residual + halo push ----
    {
        const int n  = tid & 31;
        const int oq = tid >> 5;
        #pragma unroll
        for (int oi = 0; oi < 4; oi++){
            const int o = oq + (oi << 5);
            const int r = n + 4;
            const float* Po = P + o*P_STR;
            float v  = Po[r - D] + Po[P_TAP + r] + Po[2*P_TAP + r + D];
            float hn = fmaxf(v + cb[o], 0.f) + Hm[o*HM_STR + r];
            Hm[o*HM_STR + r]  = hn;
            Hh[o*HH_STRH + r] = __float2half_rn(hn);
            if (n < 4 && tg > 0)
                st_cl_f32(lPm + ((uint32_t)(o*HM_STR + 36 + n) << 2), hn);
            if (n >= 28 && tg < 3)
                st_cl_f32(rPm + ((uint32_t)(o*HM_STR + n - 28) << 2), hn);
            if (tg == 3 && n == 0){   // t = 128 -> r = 36 (its +D taps read zero cols)
                float v2 = Po[36 - D] + Po[P_TAP + 36] + Po[2*P_TAP + 36 + D];
                float h2 = fmaxf(v2 + cb[o], 0.f) + Hm[o*HM_STR + 36];
                Hm[o*HM_STR + 36]  = h2;
                Hh[o*HH_STRH + 36] = __float2half_rn(h2);
            }
        }
    }
    CLUSTER_SYNC();   // new Hm (local + DSMEM halos) visible cluster-wide
}

__global__ void __cluster_dims__(4, 1, 1) __launch_bounds__(NTHREADS, 1)
vgt_kernel(const int* __restrict__ x, const float* __restrict__ emb_w,
           const float* __restrict__ red_w, const float* __restrict__ red_b,
           const float* __restrict__ conv_w, const float* __restrict__ conv_b,
           const float* __restrict__ out_w, const float* __restrict__ out_b,
           float* __restrict__ out)
{
    extern __shared__ __align__(16) float sm[];
    __half* wsh = (__half*)sm;
    __half* Hh  = (__half*)(sm + HH_F);
    float*  Hm  = sm + HM_F;
    float*  P   = sm + P_F;

    const int tid = threadIdx.x;
    const int b   = blockIdx.x >> 2;
    const int tg  = blockIdx.x & 3;     // owns t in [tg*32, tg*32+32) (+ t=128 for tg3)

    const uint32_t smS = (uint32_t)__cvta_generic_to_shared(sm);
    const uint32_t hmA = smS + (uint32_t)(HM_F*4);
    const uint32_t lPm = (tg > 0) ? mapa32(hmA, (uint32_t)(tg - 1)) : 0u;
    const uint32_t rPm = (tg < 3) ? mapa32(hmA, (uint32_t)(tg + 1)) : 0u;

    // ---- prologue: zero H regions, reducer tables (overlay in P), W fp16, bias ----
    for (int i = tid; i < (HM_F - HH_F) + 128*HM_STR; i += NTHREADS) sm[HH_F + i] = 0.f;

    float* m1 = P;
    float* m2 = P + 1280;
    for (int idx = tid; idx < 1280; idx += NTHREADS){
        int v = idx >> 7, o = idx & 127;
        const float* rw = red_w + o*256;
        const float* ew = emb_w + v*128;
        float s1 = 0.f, s2 = 0.f;
        for (int c = 0; c < 128; c++){
            float e = ew[c];
            s1 = fmaf(rw[c],       e, s1);
            s2 = fmaf(rw[128 + c], e, s2);
        }
        m1[idx] = s1;
        m2[idx] = s2;
    }
    for (int idx = tid; idx < 3*128*128; idx += NTHREADS){
        int k = idx >> 14;
        int r = idx & 16383;
        int o = r >> 7;
        int c = r & 127;
        wsh[k*17408 + o*136 + c] = __float2half_rn(conv_w[(o*128 + c)*3 + k]);
    }
    if (tid < 128) sm[CB_F + tid] = conv_b[tid];
    __syncthreads();

    // h0 = relu(M1[x[t]] + M2[x[t+128]] + red_b), local cols r in [0,41), t=128 stays 0
    {
        const int* xb = x + b*256;
        for (int idx = tid; idx < 128*41; idx += NTHREADS){
            int c = idx / 41;
            int r = idx - c*41;
            int t = tg*32 + r - 4;
            if (t >= 0 && t < 128){
                float val = m1[xb[t]*128 + c] + m2[xb[t + 128]*128 + c] + red_b[c];
                val = fmaxf(val, 0.f);
                Hm[c*HM_STR + r]  = val;
                Hh[c*HH_STRH + r] = __float2half_rn(val);
            }
        }
    }
    __syncthreads();

    // ---- 131 residual conv iterations ----
    #pragma unroll 1
    for (int i = 0; i < 4; i++)  do_iter<1>(sm, smS, lPm, rPm, tg);
    #pragma unroll 1
    for (int i = 0; i < 4; i++)  do_iter<2>(sm, smS, lPm, rPm, tg);
    #pragma unroll 1
    for (int i = 0; i < NITER - 8; i++) do_iter<4>(sm, smS, lPm, rPm, tg);

    // ---- output head: out[b,t,o10] = out_w . Hm[:, r] + out_b ----
    {
        const int tcnt = (tg == 3) ? 33 : 32;
        for (int idx = tid; idx < tcnt*10; idx += NTHREADS){
            int tl  = idx / 10;
            int o10 = idx % 10;
            int t   = tg*32 + tl;
            int r   = 4 + tl;
            const float* wrow = out_w + o10*128;
            float s = out_b[o10];
            #pragma unroll 8
            for (int c = 0; c < 128; c++)
                s = fmaf(__ldg(wrow + c), Hm[c*HM_STR + r], s);
            out[(b*129 + t)*10 + o10] = s;
        }
    }
}

extern "C" void kernel_launch(void* const* d_in, const int* in_sizes, int n_in,
                              void* d_out, int out_size)
{
    (void)in_sizes; (void)n_in; (void)out_size;
    const int*   x      = (const int*)  d_in[0];
    const float* emb_w  = (const float*)d_in[1];
    const float* red_w  = (const float*)d_in[2];
    const float* red_b  = (const float*)d_in[3];
    const float* conv_w = (const float*)d_in[4];
    const float* conv_b = (const float*)d_in[5];
    const float* out_w  = (const float*)d_in[6];
    const float* out_b  = (const float*)d_in[7];
    float* out = (float*)d_out;

    const size_t smem = (size_t)SM_F * sizeof(float);   // 221184 B
    cudaFuncSetAttribute(vgt_kernel, cudaFuncAttributeMaxDynamicSharedMemorySize, (int)smem);
    vgt_kernel<<<NB*4, NTHREADS, smem>>>(x, emb_w, red_w, red_b,
                                         conv_w, conv_b, out_w, out_b, out);
}

// round 15
// speedup vs baseline: 2.4664x; 1.0310x over previous
#include <cuda_runtime.h>
#include <cuda_fp16.h>
#include <cstdint>

#define NB 32
#define NITER 131
#define NTHREADS 1024

// ---- smem layout (bytes) ----
// A  (W' fp16, 128 x 392 halfs, row stride 784B)   : [0, 100352)
// B  (shifted H fp16, 384 x 56 halfs, stride 112B) : [100352, 143360)
// Hm0 (fp32 128 x 45)                              : [143360, 166400)
// Hm1 (fp32 128 x 45)                              : [166400, 189440)
// cb  (128 f)                                      : [189440, 189952)
// mbarL, mbarR (u64 each)                          : [189952, 189968)
#define B_BYTE    100352u
#define HM_F      35840      // float index of Hm0
#define HM_STR    45         // floats per Hm row
#define HM_BUF_F  5760       // floats per Hm buffer
#define HM_BUF_B  23040u     // bytes per Hm buffer
#define CB_F      47360
#define MB_BYTE   189952u
#define SM_F      47496      // total floats (189984 B)

// ---------- helpers ----------
__device__ __forceinline__ uint32_t mapa32(uint32_t addr, uint32_t rank){
    uint32_t r; asm("mapa.shared::cluster.u32 %0, %1, %2;" : "=r"(r) : "r"(addr), "r"(rank));
    return r;
}
__device__ __forceinline__ void st_cl_f32(uint32_t addr, float v){
    asm volatile("st.shared::cluster.f32 [%0], %1;" :: "r"(addr), "f"(v) : "memory");
}
#define CLUSTER_SYNC() do { \
    asm volatile("barrier.cluster.arrive.aligned;" ::: "memory"); \
    asm volatile("barrier.cluster.wait.aligned;"   ::: "memory"); } while(0)

#define MBAR_INIT(mb, n)  asm volatile("mbarrier.init.shared.b64 [%0], %1;" :: "r"(mb), "r"(n) : "memory")
#define MBAR_ARRIVE_REMOTE(addr) \
    asm volatile("mbarrier.arrive.shared::cluster.b64 _, [%0];" :: "r"(addr) : "memory")
#define MBAR_WAIT(mb, ph) do { \
    uint32_t _done; \
    asm volatile("{\n\t.reg .pred p;\n\t" \
        "mbarrier.try_wait.parity.acquire.cta.shared::cta.b64 p, [%1], %2;\n\t" \
        "selp.b32 %0, 1, 0, p;\n\t}" : "=r"(_done) : "r"(mb), "r"(ph) : "memory"); \
    if (!_done){ \
        asm volatile("{\n\t.reg .pred P1;\n\tWL_%=:\n\t" \
            "mbarrier.try_wait.parity.acquire.cta.shared::cta.b64 P1, [%0], %1, 0x989680;\n\t" \
            "@P1 bra.uni WD_%=;\n\tbra.uni WL_%=;\n\tWD_%=:\n\t}" \
            :: "r"(mb), "r"(ph) : "memory"); \
    } } while(0)

__device__ __forceinline__ void ldmA(uint32_t* a, uint32_t addr){
    asm volatile("ldmatrix.sync.aligned.m8n8.x4.shared.b16 {%0,%1,%2,%3}, [%4];"
        : "=r"(a[0]), "=r"(a[1]), "=r"(a[2]), "=r"(a[3]) : "r"(addr));
}
__device__ __forceinline__ void ldmBT(uint32_t* b, uint32_t addr){
    asm volatile("ldmatrix.sync.aligned.m8n8.x2.trans.shared.b16 {%0,%1}, [%2];"
        : "=r"(b[0]), "=r"(b[1]) : "r"(addr));
}
__device__ __forceinline__ void mma16816(float* d, const uint32_t* a, const uint32_t* b){
    asm volatile("mma.sync.aligned.m16n8k16.row.col.f32.f16.f16.f32 "
        "{%0,%1,%2,%3},{%4,%5,%6,%7},{%8,%9},{%0,%1,%2,%3};"
        : "+f"(d[0]), "+f"(d[1]), "+f"(d[2]), "+f"(d[3])
        : "r"(a[0]), "r"(a[1]), "r"(a[2]), "r"(a[3]), "r"(b[0]), "r"(b[1]));
}

// One residual dilated-conv iteration, taps folded into K:
//   out[o][j] = sum_{k,c} W'[o][k*128+c] * Hm[c][j+4+(k-1)D]   (K = 384 GEMM)
// Epilogue in mma fragments: bias+relu+residual -> Hm[nxt] + DSMEM halo pushes.
// Sync: per-direction neighbor mbarriers, one round per iteration.
template<int D>
__device__ __forceinline__ void do_iter(
    float* sm, uint32_t smS, int cur, int tg, int ph,
    uint32_t lHm0, uint32_t rHm0, uint32_t mbL, uint32_t mbR,
    uint32_t lMbR, uint32_t rMbL)
{
    const int tid  = threadIdx.x;
    const int lane = tid & 31;
    const int w    = tid >> 5;
    float* Hmc = sm + HM_F + cur*HM_BUF_F;
    float* Hmn = sm + HM_F + (cur^1)*HM_BUF_F;

    // ---- wait for neighbor halo pushes of previous iteration ----
    if (tg > 0) MBAR_WAIT(mbL, ph);
    if (tg < 3) MBAR_WAIT(mbR, ph);
    asm volatile("fence.acq_rel.cluster;" ::: "memory");

    // ---- build shifted fp16 B: B[k*128+c][2pj..2pj+1] = Hm[c][2pj+4+(k-1)D ...] ----
    {
        __half2* B2 = (__half2*)((char*)sm + B_BYTE);
        #pragma unroll
        for (int ii = 0; ii < 7; ii++){
            int idx = tid + ii*NTHREADS;
            if (idx < 6528){                      // 384 rows x 17 col-pairs (cols 0..33)
                int kc = idx / 17;
                int pj = idx - kc*17;
                int k  = kc >> 7;
                int c  = kc & 127;
                int col = 2*pj + 4 + (k - 1)*D;   // in [0, 41]
                const float* hr = Hmc + c*HM_STR + col;
                B2[kc*28 + pj] = __floats2half2_rn(hr[0], hr[1]);
            }
        }
    }
    __syncthreads();

    // ---- GEMM (warps 0..23: m16 x n16, K=384) + register epilogue ----
    if (w < 24){
        const int m0 = (w / 3) * 16;
        const int n0 = (w % 3) * 16;
        uint32_t aB = smS + (uint32_t)((m0 + (lane & 15)) * 784) + ((uint32_t)(lane >> 4) << 4);
        uint32_t bB = smS + B_BYTE + (uint32_t)((lane & 15) * 112) + (uint32_t)(n0 * 2);

        float d0[4] = {0.f,0.f,0.f,0.f};
        float d1[4] = {0.f,0.f,0.f,0.f};
        #pragma unroll 4
        for (int ks = 0; ks < 24; ks++){
            uint32_t b0[2], b1[2], a[4];
            ldmBT(b0, bB + (uint32_t)ks*1792u);
            ldmBT(b1, bB + (uint32_t)ks*1792u + 16u);
            ldmA (a,  aB + (uint32_t)ks*32u);
            mma16816(d0, a, b0);
            mma16816(d1, a, b1);
        }

        const int jmax = (tg == 3) ? 33 : 32;     // j=32 is t=128 (tg3 only)
        const int r0 = lane >> 2;
        const int c0 = (lane & 3) * 2;
        const uint32_t lPn = lHm0 + (uint32_t)(cur^1)*HM_BUF_B;
        const uint32_t rPn = rHm0 + (uint32_t)(cur^1)*HM_BUF_B;

        #pragma unroll
        for (int nt = 0; nt < 2; nt++){
            const float* dd = nt ? d1 : d0;
            #pragma unroll
            for (int rh = 0; rh < 2; rh++){
                const int   o    = m0 + r0 + 8*rh;
                const float bias = sm[CB_F + o];
                #pragma unroll
                for (int e = 0; e < 2; e++){
                    const int j = n0 + 8*nt + c0 + e;
                    if (j < jmax){
                        float hn = fmaxf(dd[2*rh + e] + bias, 0.f) + Hmc[o*HM_STR + j + 4];
                        Hmn[o*HM_STR + j + 4] = hn;
                        if (j < 4 && tg > 0)
                            st_cl_f32(lPn + (uint32_t)(o*HM_STR + 36 + j)*4u, hn);
                        if (j >= 28 && j < 32 && tg < 3)
                            st_cl_f32(rPn + (uint32_t)(o*HM_STR + j - 28)*4u, hn);
                    }
                }
            }
        }
    }
    __syncthreads();

    // ---- signal neighbors: my writes (incl. their halos) are done ----
    if (tid == 0){
        asm volatile("fence.acq_rel.cluster;" ::: "memory");
        if (tg > 0) MBAR_ARRIVE_REMOTE(lMbR);
        if (tg < 3) MBAR_ARRIVE_REMOTE(rMbL);
    }
}

__global__ void __cluster_dims__(4, 1, 1) __launch_bounds__(NTHREADS, 1)
vgt_kernel(const int* __restrict__ x, const float* __restrict__ emb_w,
           const float* __restrict__ red_w, const float* __restrict__ red_b,
           const float* __restrict__ conv_w, const float* __restrict__ conv_b,
           const float* __restrict__ out_w, const float* __restrict__ out_b,
           float* __restrict__ out)
{
    extern __shared__ __align__(16) float sm[];
    __half* wsh = (__half*)sm;                   // A region

    const int tid = threadIdx.x;
    const int b   = blockIdx.x >> 2;
    const int tg  = blockIdx.x & 3;              // owns t in [tg*32, tg*32+32) (+ t=128 for tg3)

    const uint32_t smS = (uint32_t)__cvta_generic_to_shared(sm);
    const uint32_t mbL = smS + MB_BYTE;
    const uint32_t mbR = mbL + 8u;
    const uint32_t lMbR = (tg > 0) ? mapa32(mbR, (uint32_t)(tg - 1)) : 0u;
    const uint32_t rMbL = (tg < 3) ? mapa32(mbL, (uint32_t)(tg + 1)) : 0u;
    const uint32_t lHm0 = (tg > 0) ? mapa32(smS + HM_F*4u, (uint32_t)(tg - 1)) : 0u;
    const uint32_t rHm0 = (tg < 3) ? mapa32(smS + HM_F*4u, (uint32_t)(tg + 1)) : 0u;

    // ---- prologue: zero both Hm buffers; reducer tables in B region ----
    for (int i = tid; i < 2*HM_BUF_F; i += NTHREADS) sm[HM_F + i] = 0.f;

    float* m1 = sm + 25088;                      // overlay in B region
    float* m2 = m1 + 1280;
    for (int idx = tid; idx < 1280; idx += NTHREADS){
        int v = idx >> 7, o = idx & 127;
        const float* rw = red_w + o*256;
        const float* ew = emb_w + v*128;
        float s1 = 0.f, s2 = 0.f;
        for (int c = 0; c < 128; c++){
            float e = ew[c];
            s1 = fmaf(rw[c],       e, s1);
            s2 = fmaf(rw[128 + c], e, s2);
        }
        m1[idx] = s1;
        m2[idx] = s2;
    }
    __syncthreads();

    // h0 = relu(M1[x[t]] + M2[x[t+128]] + red_b) into Hm0, local cols [0,40)
    {
        float* Hm0 = sm + HM_F;
        const int* xb = x + b*256;
        for (int idx = tid; idx < 128*40; idx += NTHREADS){
            int c = idx / 40;
            int r = idx - c*40;
            int t = tg*32 + r - 4;
            if (t >= 0 && t < 128){
                float val = m1[xb[t]*128 + c] + m2[xb[t + 128]*128 + c] + red_b[c];
                Hm0[c*HM_STR + r] = fmaxf(val, 0.f);
            }
        }
    }
    __syncthreads();   // tables no longer needed; B region free

    // W' fp16: wsh[o*392 + k*128 + c] = conv_w[(o*128+c)*3 + k]
    for (int idx = tid; idx < 3*128*128; idx += NTHREADS){
        int k = idx >> 14;
        int r = idx & 16383;
        int o = r >> 7;
        int c = r & 127;
        wsh[o*392 + k*128 + c] = __float2half_rn(conv_w[(o*128 + c)*3 + k]);
    }
    if (tid < 128) sm[CB_F + tid] = conv_b[tid];
    if (tid == 0){ MBAR_INIT(mbL, 1); MBAR_INIT(mbR, 1); }
    __syncthreads();
    CLUSTER_SYNC();    // mbar init + everything visible cluster-wide

    // prime phase 0 (iteration 0 needs no peer data — h0 includes own halos)
    if (tid == 0){
        if (tg > 0) MBAR_ARRIVE_REMOTE(lMbR);
        if (tg < 3) MBAR_ARRIVE_REMOTE(rMbL);
    }

    // ---- 131 residual conv iterations ----
    int cur = 0, ph = 0;
    #pragma unroll 1
    for (int i = 0; i < 4; i++){
        do_iter<1>(sm, smS, cur, tg, ph, lHm0, rHm0, mbL, mbR, lMbR, rMbL);
        cur ^= 1; ph ^= 1;
    }
    #pragma unroll 1
    for (int i = 0; i < 4; i++){
        do_iter<2>(sm, smS, cur, tg, ph, lHm0, rHm0, mbL, mbR, lMbR, rMbL);
        cur ^= 1; ph ^= 1;
    }
    #pragma unroll 1
    for (int i = 0; i < NITER - 8; i++){
        do_iter<4>(sm, smS, cur, tg, ph, lHm0, rHm0, mbL, mbR, lMbR, rMbL);
        cur ^= 1; ph ^= 1;
    }

    // ---- output head: out[b,t,o10] = out_w . Hm[:, r] + out_b (own cols only) ----
    {
        const float* Hmf = sm + HM_F + cur*HM_BUF_F;
        const int tcnt = (tg == 3) ? 33 : 32;
        for (int idx = tid; idx < tcnt*10; idx += NTHREADS){
            int tl  = idx / 10;
            int o10 = idx % 10;
            int t   = tg*32 + tl;
            int r   = 4 + tl;
            const float* wrow = out_w + o10*128;
            float s = out_b[o10];
            #pragma unroll 8
            for (int c = 0; c < 128; c++)
                s = fmaf(__ldg(wrow + c), Hmf[c*HM_STR + r], s);
            out[(b*129 + t)*10 + o10] = s;
        }
    }

    CLUSTER_SYNC();    // keep smem alive for in-flight peer mbar arrivals / pushes
}

extern "C" void kernel_launch(void* const* d_in, const int* in_sizes, int n_in,
                              void* d_out, int out_size)
{
    (void)in_sizes; (void)n_in; (void)out_size;
    const int*   x      = (const int*)  d_in[0];
    const float* emb_w  = (const float*)d_in[1];
    const float* red_w  = (const float*)d_in[2];
    const float* red_b  = (const float*)d_in[3];
    const float* conv_w = (const float*)d_in[4];
    const float* conv_b = (const float*)d_in[5];
    const float* out_w  = (const float*)d_in[6];
    const float* out_b  = (const float*)d_in[7];
    float* out = (float*)d_out;

    const size_t smem = (size_t)SM_F * sizeof(float);   // 189984 B
    cudaFuncSetAttribute(vgt_kernel, cudaFuncAttributeMaxDynamicSharedMemorySize, (int)smem);
    vgt_kernel<<<NB*4, NTHREADS, smem>>>(x, emb_w, red_w, red_b,
                                         conv_w, conv_b, out_w, out_b, out);
}

// round 16
// speedup vs baseline: 2.7504x; 1.1151x over previous
#include <cuda_runtime.h>
#include <cuda_fp16.h>
#include <cstdint>

#define NB 32
#define NITER 131
#define NTHREADS 512

// ---- smem layout (bytes) ----
#define B_BYTE    100352u
#define HM_F      35840      // float index of Hm0
#define HM_STR    45         // floats per Hm row
#define HM_BUF_F  5760       // floats per Hm buffer
#define HM_BUF_B  23040u     // bytes per Hm buffer
#define CB_F      47360
#define MB_BYTE   189952u
#define SM_F      47496      // total floats (189984 B)

// ---------- helpers ----------
__device__ __forceinline__ uint32_t mapa32(uint32_t addr, uint32_t rank){
    uint32_t r; asm("mapa.shared::cluster.u32 %0, %1, %2;" : "=r"(r) : "r"(addr), "r"(rank));
    return r;
}
__device__ __forceinline__ void st_cl_f32(uint32_t addr, float v){
    asm volatile("st.shared::cluster.f32 [%0], %1;" :: "r"(addr), "f"(v) : "memory");
}
#define CLUSTER_SYNC() do { \
    asm volatile("barrier.cluster.arrive.aligned;" ::: "memory"); \
    asm volatile("barrier.cluster.wait.aligned;"   ::: "memory"); } while(0)

#define MBAR_INIT(mb, n)  asm volatile("mbarrier.init.shared.b64 [%0], %1;" :: "r"(mb), "r"(n) : "memory")
#define MBAR_ARRIVE_REMOTE(addr) \
    asm volatile("mbarrier.arrive.shared::cluster.b64 _, [%0];" :: "r"(addr) : "memory")
#define MBAR_WAIT(mb, ph) do { \
    uint32_t _done; \
    asm volatile("{\n\t.reg .pred p;\n\t" \
        "mbarrier.try_wait.parity.acquire.cta.shared::cta.b64 p, [%1], %2;\n\t" \
        "selp.b32 %0, 1, 0, p;\n\t}" : "=r"(_done) : "r"(mb), "r"(ph) : "memory"); \
    if (!_done){ \
        asm volatile("{\n\t.reg .pred P1;\n\tWL_%=:\n\t" \
            "mbarrier.try_wait.parity.acquire.cta.shared::cta.b64 P1, [%0], %1, 0x989680;\n\t" \
            "@P1 bra.uni WD_%=;\n\tbra.uni WL_%=;\n\tWD_%=:\n\t}" \
            :: "r"(mb), "r"(ph) : "memory"); \
    } } while(0)

__device__ __forceinline__ void ldmA(uint32_t* a, uint32_t addr){
    asm volatile("ldmatrix.sync.aligned.m8n8.x4.shared.b16 {%0,%1,%2,%3}, [%4];"
        : "=r"(a[0]), "=r"(a[1]), "=r"(a[2]), "=r"(a[3]) : "r"(addr));
}
__device__ __forceinline__ void ldmB4(uint32_t* b, uint32_t addr){
    asm volatile("ldmatrix.sync.aligned.m8n8.x4.trans.shared.b16 {%0,%1,%2,%3}, [%4];"
        : "=r"(b[0]), "=r"(b[1]), "=r"(b[2]), "=r"(b[3]) : "r"(addr));
}
__device__ __forceinline__ void ldmBT(uint32_t* b, uint32_t addr){
    asm volatile("ldmatrix.sync.aligned.m8n8.x2.trans.shared.b16 {%0,%1}, [%2];"
        : "=r"(b[0]), "=r"(b[1]) : "r"(addr));
}
__device__ __forceinline__ void mma16816(float* d, const uint32_t* a, const uint32_t* b){
    asm volatile("mma.sync.aligned.m16n8k16.row.col.f32.f16.f16.f32 "
        "{%0,%1,%2,%3},{%4,%5,%6,%7},{%8,%9},{%0,%1,%2,%3};"
        : "+f"(d[0]), "+f"(d[1]), "+f"(d[2]), "+f"(d[3])
        : "r"(a[0]), "r"(a[1]), "r"(a[2]), "r"(a[3]), "r"(b[0]), "r"(b[1]));
}

// One residual dilated-conv iteration, taps folded into K (K=384 GEMM).
// 16 warps: m-tile = w>>1 (m16), n-half = w&1 (n24 for nh0, n16 for nh1).
// A fragments for ks 0..11 are register-resident (loaded once in the prologue).
template<int D>
__device__ __forceinline__ void do_iter(
    float* sm, uint32_t smS, int cur, int tg, int ph,
    uint32_t lHm0, uint32_t rHm0, uint32_t mbL, uint32_t mbR,
    uint32_t lMbR, uint32_t rMbL,
    const uint32_t (&Areg)[48], uint32_t aB)
{
    const int tid  = threadIdx.x;
    const int lane = tid & 31;
    const int w    = tid >> 5;
    float* Hmc = sm + HM_F + cur*HM_BUF_F;
    float* Hmn = sm + HM_F + (cur^1)*HM_BUF_F;

    // ---- wait for neighbor halo pushes of previous iteration ----
    if (tg > 0) MBAR_WAIT(mbL, ph);
    if (tg < 3) MBAR_WAIT(mbR, ph);
    asm volatile("fence.acq_rel.cluster;" ::: "memory");

    // ---- build shifted fp16 B: B[k*128+c][2pj..2pj+1] = Hm[c][2pj+4+(k-1)D ...] ----
    {
        __half2* B2 = (__half2*)((char*)sm + B_BYTE);
        #pragma unroll
        for (int ii = 0; ii < 13; ii++){
            int idx = tid + ii*NTHREADS;
            if (idx < 6528){                      // 384 rows x 17 col-pairs (cols 0..33)
                int kc = idx / 17;
                int pj = idx - kc*17;
                int k  = kc >> 7;
                int c  = kc & 127;
                int col = 2*pj + 4 + (k - 1)*D;   // in [0, 41]
                const float* hr = Hmc + c*HM_STR + col;
                B2[kc*28 + pj] = __floats2half2_rn(hr[0], hr[1]);
            }
        }
    }
    __syncthreads();

    // ---- GEMM: warp w -> m0=(w>>1)*16, nh=w&1 (n0 = nh*24), K=384 ----
    {
        const int m0 = (w >> 1) << 4;
        const int nh = w & 1;
        const int n0 = nh * 24;
        const uint32_t bB4 = smS + B_BYTE + (uint32_t)((lane & 15)*112)
                           + ((uint32_t)(lane >> 4) << 4) + (uint32_t)(n0*2);
        const uint32_t bB2 = smS + B_BYTE + (uint32_t)((lane & 15)*112)
                           + (uint32_t)((n0 + 16)*2);

        float d[3][4];
        #pragma unroll
        for (int g = 0; g < 3; g++)
            #pragma unroll
            for (int j = 0; j < 4; j++) d[g][j] = 0.f;

        #pragma unroll
        for (int ks = 0; ks < 24; ks++){
            uint32_t bb[4];
            ldmB4(bb, bB4 + (uint32_t)ks*1792u);
            uint32_t b2[2];
            if (nh == 0) ldmBT(b2, bB2 + (uint32_t)ks*1792u);
            uint32_t at[4];
            const uint32_t* ap;
            if (ks < 12) ap = &Areg[ks*4];
            else { ldmA(at, aB + (uint32_t)ks*32u); ap = at; }
            mma16816(d[0], ap, bb);
            mma16816(d[1], ap, bb + 2);
            if (nh == 0) mma16816(d[2], ap, b2);
        }

        // ---- register epilogue: bias+relu+residual -> Hmn + DSMEM halo pushes ----
        const int jmax = (tg == 3) ? 33 : 32;
        const int r0 = lane >> 2;
        const int c0 = (lane & 3) * 2;
        const int ng = (nh == 0) ? 3 : 2;
        const uint32_t lPn = lHm0 + (uint32_t)(cur^1)*HM_BUF_B;
        const uint32_t rPn = rHm0 + (uint32_t)(cur^1)*HM_BUF_B;

        #pragma unroll
        for (int g = 0; g < 3; g++){
            if (g < ng){
                #pragma unroll
                for (int rh = 0; rh < 2; rh++){
                    const int   o    = m0 + r0 + 8*rh;
                    const float bias = sm[CB_F + o];
                    #pragma unroll
                    for (int e = 0; e < 2; e++){
                        const int j = n0 + 8*g + c0 + e;
                        if (j < jmax){
                            float hn = fmaxf(d[g][2*rh + e] + bias, 0.f) + Hmc[o*HM_STR + j + 4];
                            Hmn[o*HM_STR + j + 4] = hn;
                            if (j < 4 && tg > 0)
                                st_cl_f32(lPn + (uint32_t)(o*HM_STR + 36 + j)*4u, hn);
                            if (j >= 28 && j < 32 && tg < 3)
                                st_cl_f32(rPn + (uint32_t)(o*HM_STR + j - 28)*4u, hn);
                        }
                    }
                }
            }
        }
    }
    __syncthreads();

    // ---- signal neighbors ----
    if (tid == 0){
        asm volatile("fence.acq_rel.cluster;" ::: "memory");
        if (tg > 0) MBAR_ARRIVE_REMOTE(lMbR);
        if (tg < 3) MBAR_ARRIVE_REMOTE(rMbL);
    }
}

__global__ void __cluster_dims__(4, 1, 1) __launch_bounds__(NTHREADS, 1)
vgt_kernel(const int* __restrict__ x, const float* __restrict__ emb_w,
           const float* __restrict__ red_w, const float* __restrict__ red_b,
           const float* __restrict__ conv_w, const float* __restrict__ conv_b,
           const float* __restrict__ out_w, const float* __restrict__ out_b,
           float* __restrict__ out)
{
    extern __shared__ __align__(16) float sm[];
    __half* wsh = (__half*)sm;                   // A region

    const int tid = threadIdx.x;
    const int lane = tid & 31;
    const int w    = tid >> 5;
    const int b   = blockIdx.x >> 2;
    const int tg  = blockIdx.x & 3;              // owns t in [tg*32, tg*32+32) (+ t=128 for tg3)

    const uint32_t smS = (uint32_t)__cvta_generic_to_shared(sm);
    const uint32_t mbL = smS + MB_BYTE;
    const uint32_t mbR = mbL + 8u;
    const uint32_t lMbR = (tg > 0) ? mapa32(mbR, (uint32_t)(tg - 1)) : 0u;
    const uint32_t rMbL = (tg < 3) ? mapa32(mbL, (uint32_t)(tg + 1)) : 0u;
    const uint32_t lHm0 = (tg > 0) ? mapa32(smS + HM_F*4u, (uint32_t)(tg - 1)) : 0u;
    const uint32_t rHm0 = (tg < 3) ? mapa32(smS + HM_F*4u, (uint32_t)(tg + 1)) : 0u;

    // ---- prologue: zero both Hm buffers; reducer tables in B region ----
    for (int i = tid; i < 2*HM_BUF_F; i += NTHREADS) sm[HM_F + i] = 0.f;

    float* m1 = sm + 25088;                      // overlay in B region
    float* m2 = m1 + 1280;
    for (int idx = tid; idx < 1280; idx += NTHREADS){
        int v = idx >> 7, o = idx & 127;
        const float* rw = red_w + o*256;
        const float* ew = emb_w + v*128;
        float s1 = 0.f, s2 = 0.f;
        for (int c = 0; c < 128; c++){
            float e = ew[c];
            s1 = fmaf(rw[c],       e, s1);
            s2 = fmaf(rw[128 + c], e, s2);
        }
        m1[idx] = s1;
        m2[idx] = s2;
    }
    __syncthreads();

    // h0 = relu(M1[x[t]] + M2[x[t+128]] + red_b) into Hm0, local cols [0,40)
    {
        float* Hm0 = sm + HM_F;
        const int* xb = x + b*256;
        for (int idx = tid; idx < 128*40; idx += NTHREADS){
            int c = idx / 40;
            int r = idx - c*40;
            int t = tg*32 + r - 4;
            if (t >= 0 && t < 128){
                float val = m1[xb[t]*128 + c] + m2[xb[t + 128]*128 + c] + red_b[c];
                Hm0[c*HM_STR + r] = fmaxf(val, 0.f);
            }
        }
    }
    __syncthreads();   // tables no longer needed; B region free

    // W' fp16: wsh[o*392 + k*128 + c] = conv_w[(o*128+c)*3 + k]
    for (int idx = tid; idx < 3*128*128; idx += NTHREADS){
        int k = idx >> 14;
        int r = idx & 16383;
        int o = r >> 7;
        int c = r & 127;
        wsh[o*392 + k*128 + c] = __float2half_rn(conv_w[(o*128 + c)*3 + k]);
    }
    if (tid < 128) sm[CB_F + tid] = conv_b[tid];
    if (tid == 0){ MBAR_INIT(mbL, 1); MBAR_INIT(mbR, 1); }
    __syncthreads();

    // ---- load resident A fragments (ks 0..11) — weights are loop-invariant ----
    const int m0w = (w >> 1) << 4;
    const uint32_t aB = smS + (uint32_t)((m0w + (lane & 15))*784)
                      + ((uint32_t)(lane >> 4) << 4);
    uint32_t Areg[48];
    #pragma unroll
    for (int ks = 0; ks < 12; ks++) ldmA(&Areg[ks*4], aB + (uint32_t)ks*32u);

    CLUSTER_SYNC();    // mbar init + everything visible cluster-wide

    // prime phase 0 (iteration 0 needs no peer data — h0 includes own halos)
    if (tid == 0){
        if (tg > 0) MBAR_ARRIVE_REMOTE(lMbR);
        if (tg < 3) MBAR_ARRIVE_REMOTE(rMbL);
    }

    // ---- 131 residual conv iterations ----
    int cur = 0, ph = 0;
    #pragma unroll 1
    for (int i = 0; i < 4; i++){
        do_iter<1>(sm, smS, cur, tg, ph, lHm0, rHm0, mbL, mbR, lMbR, rMbL, Areg, aB);
        cur ^= 1; ph ^= 1;
    }
    #pragma unroll 1
    for (int i = 0; i < 4; i++){
        do_iter<2>(sm, smS, cur, tg, ph, lHm0, rHm0, mbL, mbR, lMbR, rMbL, Areg, aB);
        cur ^= 1; ph ^= 1;
    }
    #pragma unroll 1
    for (int i = 0; i < NITER - 8; i++){
        do_iter<4>(sm, smS, cur, tg, ph, lHm0, rHm0, mbL, mbR, lMbR, rMbL, Areg, aB);
        cur ^= 1; ph ^= 1;
    }

    // ---- output head: out[b,t,o10] = out_w . Hm[:, r] + out_b (own cols only) ----
    {
        const float* Hmf = sm + HM_F + cur*HM_BUF_F;
        const int tcnt = (tg == 3) ? 33 : 32;
        for (int idx = tid; idx < tcnt*10; idx += NTHREADS){
            int tl  = idx / 10;
            int o10 = idx % 10;
            int t   = tg*32 + tl;
            int r   = 4 + tl;
            const float* wrow = out_w + o10*128;
            float s = out_b[o10];
            #pragma unroll 8
            for (int c = 0; c < 128; c++)
                s = fmaf(__ldg(wrow + c), Hmf[c*HM_STR + r], s);
            out[(b*129 + t)*10 + o10] = s;
        }
    }

    CLUSTER_SYNC();    // keep smem alive for in-flight peer mbar arrivals / pushes
}

extern "C" void kernel_launch(void* const* d_in, const int* in_sizes, int n_in,
                              void* d_out, int out_size)
{
    (void)in_sizes; (void)n_in; (void)out_size;
    const int*   x      = (const int*)  d_in[0];
    const float* emb_w  = (const float*)d_in[1];
    const float* red_w  = (const float*)d_in[2];
    const float* red_b  = (const float*)d_in[3];
    const float* conv_w = (const float*)d_in[4];
    const float* conv_b = (const float*)d_in[5];
    const float* out_w  = (const float*)d_in[6];
    const float* out_b  = (const float*)d_in[7];
    float* out = (float*)d_out;

    const size_t smem = (size_t)SM_F * sizeof(float);   // 189984 B
    cudaFuncSetAttribute(vgt_kernel, cudaFuncAttributeMaxDynamicSharedMemorySize, (int)smem);
    vgt_kernel<<<NB*4, NTHREADS, smem>>>(x, emb_w, red_w, red_b,
                                         conv_w, conv_b, out_w, out_b, out);
}

// round 17
// speedup vs baseline: 3.3572x; 1.2206x over previous
#include <cuda_runtime.h>
#include <cuda_fp16.h>
#include <cstdint>

#define NB 32
#define NITER 131
#define NTHREADS 512

// ---- smem layout (bytes) ----
// A  (W' fp16, 128 x 392 halfs, stride 784B)            : [0, 100352)
// B  (2 shifted blocks, 128 x 56 halfs each, 14336B ea) : [100352, 129024)
// Hh (fp16 H mirror, 2 bufs, 128 x 56 halfs, 14336B ea) : [129024, 157696)
// Hm (fp32, single buf, 128 x 45)                       : [157696, 180736)
// cb (128 f)                                            : [180736, 181248)
// mbarL, mbarR                                          : [181248, 181264)
#define B_BYTE    100352u
#define HH_BYTE   129024u
#define HH_BUF_B  14336u
#define HM_F      39424      // float index of Hm
#define HM_STR    45
#define CB_F      45184
#define MB_BYTE   181248u
#define SM_F      45320      // 181280 B total

// ---------- helpers ----------
__device__ __forceinline__ uint32_t mapa32(uint32_t addr, uint32_t rank){
    uint32_t r; asm("mapa.shared::cluster.u32 %0, %1, %2;" : "=r"(r) : "r"(addr), "r"(rank));
    return r;
}
__device__ __forceinline__ void st_cl_u32(uint32_t addr, uint32_t v){
    asm volatile("st.shared::cluster.u32 [%0], %1;" :: "r"(addr), "r"(v) : "memory");
}
__device__ __forceinline__ uint32_t h2u(__half2 h){
    uint32_t u; __builtin_memcpy(&u, &h, 4); return u;
}
#define CLUSTER_SYNC() do { \
    asm volatile("barrier.cluster.arrive.aligned;" ::: "memory"); \
    asm volatile("barrier.cluster.wait.aligned;"   ::: "memory"); } while(0)

#define MBAR_INIT(mb, n)  asm volatile("mbarrier.init.shared.b64 [%0], %1;" :: "r"(mb), "r"(n) : "memory")
#define MBAR_ARRIVE_REMOTE(addr) \
    asm volatile("mbarrier.arrive.shared::cluster.b64 _, [%0];" :: "r"(addr) : "memory")
#define MBAR_WAIT(mb, ph) do { \
    uint32_t _done; \
    asm volatile("{\n\t.reg .pred p;\n\t" \
        "mbarrier.try_wait.parity.acquire.cta.shared::cta.b64 p, [%1], %2;\n\t" \
        "selp.b32 %0, 1, 0, p;\n\t}" : "=r"(_done) : "r"(mb), "r"(ph) : "memory"); \
    if (!_done){ \
        asm volatile("{\n\t.reg .pred P1;\n\tWL_%=:\n\t" \
            "mbarrier.try_wait.parity.acquire.cta.shared::cta.b64 P1, [%0], %1, 0x989680;\n\t" \
            "@P1 bra.uni WD_%=;\n\tbra.uni WL_%=;\n\tWD_%=:\n\t}" \
            :: "r"(mb), "r"(ph) : "memory"); \
    } } while(0)

__device__ __forceinline__ void ldmA(uint32_t* a, uint32_t addr){
    asm volatile("ldmatrix.sync.aligned.m8n8.x4.shared.b16 {%0,%1,%2,%3}, [%4];"
        : "=r"(a[0]), "=r"(a[1]), "=r"(a[2]), "=r"(a[3]) : "r"(addr));
}
__device__ __forceinline__ void ldmB4(uint32_t* b, uint32_t addr){
    asm volatile("ldmatrix.sync.aligned.m8n8.x4.trans.shared.b16 {%0,%1,%2,%3}, [%4];"
        : "=r"(b[0]), "=r"(b[1]), "=r"(b[2]), "=r"(b[3]) : "r"(addr));
}
__device__ __forceinline__ void ldmBT(uint32_t* b, uint32_t addr){
    asm volatile("ldmatrix.sync.aligned.m8n8.x2.trans.shared.b16 {%0,%1}, [%2];"
        : "=r"(b[0]), "=r"(b[1]) : "r"(addr));
}
__device__ __forceinline__ void mma16816(float* d, const uint32_t* a, const uint32_t* b){
    asm volatile("mma.sync.aligned.m16n8k16.row.col.f32.f16.f16.f32 "
        "{%0,%1,%2,%3},{%4,%5,%6,%7},{%8,%9},{%0,%1,%2,%3};"
        : "+f"(d[0]), "+f"(d[1]), "+f"(d[2]), "+f"(d[3])
        : "r"(a[0]), "r"(a[1]), "r"(a[2]), "r"(a[3]), "r"(b[0]), "r"(b[1]));
}

// One residual dilated-conv iteration (K=384 fused).
// B blocks: k=0 (shift -D), k=2 (shift +D). k=1 reads the Hh mirror directly.
// Hh pos mapping: local col r -> half index r+4 (owned j at pos j+8, 16B aligned).
template<int D>
__device__ __forceinline__ void do_iter(
    float* sm, uint32_t smS, int cur, int tg, int ph,
    uint32_t lHhB, uint32_t rHhB, uint32_t mbL, uint32_t mbR,
    uint32_t lMbR, uint32_t rMbL,
    const uint32_t (&Areg)[48], uint32_t aB)
{
    const int tid  = threadIdx.x;
    const int lane = tid & 31;
    const int w    = tid >> 5;

    if (tg > 0) MBAR_WAIT(mbL, ph);
    if (tg < 3) MBAR_WAIT(mbR, ph);
    asm volatile("fence.acq_rel.cluster;" ::: "memory");

    const __half* HhC = (const __half*)((char*)sm + HH_BYTE + (uint32_t)cur*HH_BUF_B);
    __half*       HhN = (__half*)((char*)sm + HH_BYTE + (uint32_t)(cur^1)*HH_BUF_B);
    float* Hm = sm + HM_F;

    // ---- B-build: 2 shifted half2 copies of Hh (4352 items) ----
    {
        __half2* Bp = (__half2*)((char*)sm + B_BYTE);
        #pragma unroll
        for (int ii = 0; ii < 9; ii++){
            int idx = tid + ii*NTHREADS;
            if (idx < 4352){
                int row = idx / 17;            // 0..255
                int pj  = idx - row*17;        // 0..16
                int kb  = row >> 7;
                int c   = row & 127;
                int pos = 2*pj + 8 + (kb ? D : -D);
                __half2 v;
                if (D == 1)
                    v = __halves2half2(HhC[c*56 + pos], HhC[c*56 + pos + 1]);
                else
                    v = *(const __half2*)(HhC + c*56 + pos);
                Bp[kb*3584 + c*28 + pj] = v;
            }
        }
    }
    __syncthreads();

    // ---- GEMM (16 warps: m-tile = w>>1, nh = w&1) + register epilogue ----
    {
        const int m0 = (w >> 1) << 4;
        const int nh = w & 1;
        const uint32_t rowB = (uint32_t)((lane & 15)*112);
        const uint32_t b0s = smS + B_BYTE;
        const uint32_t b1s = smS + HH_BYTE + (uint32_t)cur*HH_BUF_B + 16u;  // pos 8 = j0
        const uint32_t b2s = smS + B_BYTE + 14336u;

        float d[3][4];
        #pragma unroll
        for (int g = 0; g < 3; g++)
            #pragma unroll
            for (int j = 0; j < 4; j++) d[g][j] = 0.f;

        #pragma unroll
        for (int ks = 0; ks < 24; ks++){
            const uint32_t base = (ks < 8)  ? (b0s + (uint32_t)ks*1792u)
                                : (ks < 16) ? (b1s + (uint32_t)(ks-8)*1792u)
                                :             (b2s + (uint32_t)(ks-16)*1792u);
            uint32_t at[4];
            const uint32_t* ap;
            if (ks < 12) ap = &Areg[ks*4];
            else { ldmA(at, aB + (uint32_t)ks*32u); ap = at; }
            if (nh == 0){
                uint32_t bb[4], b2[2];
                ldmB4(bb, base + rowB + ((uint32_t)(lane >> 4) << 4));  // cols 0..15
                ldmBT(b2, base + rowB + 32u);                            // cols 16..23
                mma16816(d[0], ap, bb);
                mma16816(d[1], ap, bb + 2);
                mma16816(d[2], ap, b2);
            } else {
                uint32_t b2[2];
                ldmBT(b2, base + rowB + 48u);                            // cols 24..31
                mma16816(d[0], ap, b2);
                if (tg == 3){
                    uint32_t b3[2];
                    ldmBT(b3, base + rowB + 64u);                        // cols 32..39
                    mma16816(d[1], ap, b3);
                }
            }
        }

        // ---- epilogue: bias+relu+residual -> Hm, Hh(nxt), fp16 halo pushes ----
        const int r0 = lane >> 2;
        const int c0 = (lane & 3) * 2;
        const int ng = (nh == 0) ? 3 : ((tg == 3) ? 2 : 1);
        const uint32_t lN = lHhB + (uint32_t)(cur^1)*HH_BUF_B;
        const uint32_t rN = rHhB + (uint32_t)(cur^1)*HH_BUF_B;

        #pragma unroll
        for (int g = 0; g < 3; g++){
            if (g < ng){
                const int jb = (nh ? 24 : 0) + 8*g + c0;
                #pragma unroll
                for (int rh = 0; rh < 2; rh++){
                    const int   o    = m0 + r0 + 8*rh;
                    const float bias = sm[CB_F + o];
                    if (jb < 32){
                        float hn0 = fmaxf(d[g][2*rh+0] + bias, 0.f) + Hm[o*HM_STR + jb + 4];
                        float hn1 = fmaxf(d[g][2*rh+1] + bias, 0.f) + Hm[o*HM_STR + jb + 5];
                        Hm[o*HM_STR + jb + 4] = hn0;
                        Hm[o*HM_STR + jb + 5] = hn1;
                        __half2 hh = __floats2half2_rn(hn0, hn1);
                        *(__half2*)(HhN + o*56 + jb + 8) = hh;
                        if (jb < 4 && tg > 0)
                            st_cl_u32(lN + (uint32_t)(o*56 + 40 + jb)*2u, h2u(hh));
                        if (jb >= 28 && tg < 3)
                            st_cl_u32(rN + (uint32_t)(o*56 + jb - 24)*2u, h2u(hh));
                    } else if (jb == 32){   // tg3 only (ng gate): t = 128
                        float hn0 = fmaxf(d[g][2*rh+0] + bias, 0.f) + Hm[o*HM_STR + 36];
                        Hm[o*HM_STR + 36] = hn0;
                        HhN[o*56 + 40] = __float2half_rn(hn0);
                    }
                }
            }
        }
    }
    __syncthreads();

    if (tid == 0){
        asm volatile("fence.acq_rel.cluster;" ::: "memory");
        if (tg > 0) MBAR_ARRIVE_REMOTE(lMbR);
        if (tg < 3) MBAR_ARRIVE_REMOTE(rMbL);
    }
}

__global__ void __cluster_dims__(4, 1, 1) __launch_bounds__(NTHREADS, 1)
vgt_kernel(const int* __restrict__ x, const float* __restrict__ emb_w,
           const float* __restrict__ red_w, const float* __restrict__ red_b,
           const float* __restrict__ conv_w, const float* __restrict__ conv_b,
           const float* __restrict__ out_w, const float* __restrict__ out_b,
           float* __restrict__ out)
{
    extern __shared__ __align__(16) float sm[];
    __half* wsh = (__half*)sm;                   // A region

    const int tid  = threadIdx.x;
    const int lane = tid & 31;
    const int w    = tid >> 5;
    const int b    = blockIdx.x >> 2;
    const int tg   = blockIdx.x & 3;             // owns t in [tg*32, tg*32+32) (+ t=128 for tg3)

    const uint32_t smS = (uint32_t)__cvta_generic_to_shared(sm);
    const uint32_t mbL = smS + MB_BYTE;
    const uint32_t mbR = mbL + 8u;
    const uint32_t lMbR = (tg > 0) ? mapa32(mbR, (uint32_t)(tg - 1)) : 0u;
    const uint32_t rMbL = (tg < 3) ? mapa32(mbL, (uint32_t)(tg + 1)) : 0u;
    const uint32_t lHhB = (tg > 0) ? mapa32(smS + HH_BYTE, (uint32_t)(tg - 1)) : 0u;
    const uint32_t rHhB = (tg < 3) ? mapa32(smS + HH_BYTE, (uint32_t)(tg + 1)) : 0u;

    // ---- prologue: zero Hh (both bufs) + Hm; reducer tables in B region ----
    for (int i = tid; i < 7168; i += NTHREADS) sm[32256 + i] = 0.f;   // Hh region
    for (int i = tid; i < 5760; i += NTHREADS) sm[HM_F + i] = 0.f;

    float* m1 = sm + 25088;                      // overlay in B region
    float* m2 = m1 + 1280;
    for (int idx = tid; idx < 1280; idx += NTHREADS){
        int v = idx >> 7, o = idx & 127;
        const float* rw = red_w + o*256;
        const float* ew = emb_w + v*128;
        float s1 = 0.f, s2 = 0.f;
        for (int c = 0; c < 128; c++){
            float e = ew[c];
            s1 = fmaf(rw[c],       e, s1);
            s2 = fmaf(rw[128 + c], e, s2);
        }
        m1[idx] = s1;
        m2[idx] = s2;
    }
    __syncthreads();

    // h0 into Hm + Hh buf0 (local cols [0,40) incl. halos)
    {
        __half* Hh0 = (__half*)((char*)sm + HH_BYTE);
        const int* xb = x + b*256;
        for (int idx = tid; idx < 128*40; idx += NTHREADS){
            int c = idx / 40;
            int r = idx - c*40;
            int t = tg*32 + r - 4;
            if (t >= 0 && t < 128){
                float val = m1[xb[t]*128 + c] + m2[xb[t + 128]*128 + c] + red_b[c];
                val = fmaxf(val, 0.f);
                sm[HM_F + c*HM_STR + r] = val;
                Hh0[c*56 + r + 4] = __float2half_rn(val);
            }
        }
    }
    __syncthreads();   // tables no longer needed; B region free

    // W' fp16: wsh[o*392 + k*128 + c]
    for (int idx = tid; idx < 3*128*128; idx += NTHREADS){
        int k = idx >> 14;
        int r = idx & 16383;
        int o = r >> 7;
        int c = r & 127;
        wsh[o*392 + k*128 + c] = __float2half_rn(conv_w[(o*128 + c)*3 + k]);
    }
    // zero B region (stale reducer tables would feed discarded columns; keep clean)
    for (int i = tid; i < 7168; i += NTHREADS) sm[25088 + i] = 0.f;
    if (tid < 128) sm[CB_F + tid] = conv_b[tid];
    if (tid == 0){ MBAR_INIT(mbL, 1); MBAR_INIT(mbR, 1); }
    __syncthreads();

    // resident A fragments (ks 0..11)
    const int m0w = (w >> 1) << 4;
    const uint32_t aB = smS + (uint32_t)((m0w + (lane & 15))*784)
                      + ((uint32_t)(lane >> 4) << 4);
    uint32_t Areg[48];
    #pragma unroll
    for (int ks = 0; ks < 12; ks++) ldmA(&Areg[ks*4], aB + (uint32_t)ks*32u);

    CLUSTER_SYNC();

    // prime phase 0 (iteration 0 needs no peer data)
    if (tid == 0){
        if (tg > 0) MBAR_ARRIVE_REMOTE(lMbR);
        if (tg < 3) MBAR_ARRIVE_REMOTE(rMbL);
    }

    // ---- 131 residual conv iterations ----
    int cur = 0, ph = 0;
    #pragma unroll 1
    for (int i = 0; i < 4; i++){
        do_iter<1>(sm, smS, cur, tg, ph, lHhB, rHhB, mbL, mbR, lMbR, rMbL, Areg, aB);
        cur ^= 1; ph ^= 1;
    }
    #pragma unroll 1
    for (int i = 0; i < 4; i++){
        do_iter<2>(sm, smS, cur, tg, ph, lHhB, rHhB, mbL, mbR, lMbR, rMbL, Areg, aB);
        cur ^= 1; ph ^= 1;
    }
    #pragma unroll 1
    for (int i = 0; i < NITER - 8; i++){
        do_iter<4>(sm, smS, cur, tg, ph, lHhB, rHhB, mbL, mbR, lMbR, rMbL, Areg, aB);
        cur ^= 1; ph ^= 1;
    }

    // ---- output head (reads fp32 Hm, own cols only) ----
    {
        const float* Hmf = sm + HM_F;
        const int tcnt = (tg == 3) ? 33 : 32;
        for (int idx = tid; idx < tcnt*10; idx += NTHREADS){
            int tl  = idx / 10;
            int o10 = idx % 10;
            int t   = tg*32 + tl;
            int r   = 4 + tl;
            const float* wrow = out_w + o10*128;
            float s = out_b[o10];
            #pragma unroll 8
            for (int c = 0; c < 128; c++)
                s = fmaf(__ldg(wrow + c), Hmf[c*HM_STR + r], s);
            out[(b*129 + t)*10 + o10] = s;
        }
    }

    CLUSTER_SYNC();    // keep smem alive for in-flight peer pushes/arrivals
}

extern "C" void kernel_launch(void* const* d_in, const int* in_sizes, int n_in,
                              void* d_out, int out_size)
{
    (void)in_sizes; (void)n_in; (void)out_size;
    const int*   x      = (const int*)  d_in[0];
    const float* emb_w  = (const float*)d_in[1];
    const float* red_w  = (const float*)d_in[2];
    const float* red_b  = (const float*)d_in[3];
    const float* conv_w = (const float*)d_in[4];
    const float* conv_b = (const float*)d_in[5];
    const float* out_w  = (const float*)d_in[6];
    const float* out_b  = (const float*)d_in[7];
    float* out = (float*)d_out;

    const size_t smem = (size_t)SM_F * sizeof(float);   // 181280 B
    cudaFuncSetAttribute(vgt_kernel, cudaFuncAttributeMaxDynamicSharedMemorySize, (int)smem);
    vgt_kernel<<<NB*4, NTHREADS, smem>>>(x, emb_w, red_w, red_b,
                                         conv_w, conv_b, out_w, out_b, out);
}